// round 4
// baseline (speedup 1.0000x reference)
#include <cuda_runtime.h>
#include <math.h>

#define BATCH 8
#define SEQ   4096
#define DIN   64
#define HID   512
#define M_ROWS (BATCH*SEQ)

#define TQ 64
#define TK 64
#define RSCALE 0.044194173824159216f  /* 1/sqrt(512) */

// ---------------- global scratch (allocation-free rule) ----------------
__device__ float g_Q[BATCH*SEQ*HID];
__device__ float g_K[BATCH*SEQ*HID];
__device__ float g_V[BATCH*SEQ*HID];

// ---------------- fused QKV projection ----------------
// grid: (M/128, HID/128, 3); block 256; dyn smem 64KB
__global__ __launch_bounds__(256) void qkv_proj_kernel(
    const float* __restrict__ x,
    const float* __restrict__ Wq, const float* __restrict__ bq,
    const float* __restrict__ Wk, const float* __restrict__ bk,
    const float* __restrict__ Wv, const float* __restrict__ bv)
{
    extern __shared__ float psm[];
    float* sX = psm;            // [128][64]
    float* sW = psm + 128*64;   // [64][128]

    const float* Wsel; const float* bsel; float* osel;
    if (blockIdx.z == 0)      { Wsel = Wq; bsel = bq; osel = g_Q; }
    else if (blockIdx.z == 1) { Wsel = Wk; bsel = bk; osel = g_K; }
    else                      { Wsel = Wv; bsel = bv; osel = g_V; }

    const int row0 = blockIdx.x * 128;
    const int col0 = blockIdx.y * 128;
    const int tid  = threadIdx.x;

    #pragma unroll
    for (int i = 0; i < 8; i++) {
        int idx = i*256 + tid;               // float4 id 0..2047
        int r = idx >> 4, c4 = idx & 15;
        *(float4*)&sX[r*64 + c4*4] = *(const float4*)&x[(size_t)(row0+r)*DIN + c4*4];
    }
    #pragma unroll
    for (int i = 0; i < 8; i++) {
        int idx = i*256 + tid;
        int r = idx >> 5, c4 = idx & 31;
        *(float4*)&sW[r*128 + c4*4] = *(const float4*)&Wsel[(size_t)r*HID + col0 + c4*4];
    }
    __syncthreads();

    const int ty = tid >> 4, tx = tid & 15;
    float acc[8][8];
    #pragma unroll
    for (int i = 0; i < 8; i++)
        #pragma unroll
        for (int j = 0; j < 8; j++) acc[i][j] = 0.0f;

    #pragma unroll 8
    for (int k = 0; k < 64; k++) {
        float xr[8];
        #pragma unroll
        for (int i = 0; i < 8; i++) xr[i] = sX[(ty*8+i)*64 + k];
        float4 w0 = *(const float4*)&sW[k*128 + tx*8];
        float4 w1 = *(const float4*)&sW[k*128 + tx*8 + 4];
        #pragma unroll
        for (int i = 0; i < 8; i++) {
            acc[i][0] += xr[i]*w0.x; acc[i][1] += xr[i]*w0.y;
            acc[i][2] += xr[i]*w0.z; acc[i][3] += xr[i]*w0.w;
            acc[i][4] += xr[i]*w1.x; acc[i][5] += xr[i]*w1.y;
            acc[i][6] += xr[i]*w1.z; acc[i][7] += xr[i]*w1.w;
        }
    }

    float bb[8];
    #pragma unroll
    for (int j = 0; j < 8; j++) bb[j] = __ldg(&bsel[col0 + tx*8 + j]);

    #pragma unroll
    for (int i = 0; i < 8; i++) {
        float4 o0, o1;
        o0.x = acc[i][0]+bb[0]; o0.y = acc[i][1]+bb[1];
        o0.z = acc[i][2]+bb[2]; o0.w = acc[i][3]+bb[3];
        o1.x = acc[i][4]+bb[4]; o1.y = acc[i][5]+bb[5];
        o1.z = acc[i][6]+bb[6]; o1.w = acc[i][7]+bb[7];
        size_t base = (size_t)(row0 + ty*8 + i)*HID + col0 + tx*8;
        *(float4*)&osel[base]     = o0;
        *(float4*)&osel[base + 4] = o1;
    }
}

// ---------------- flash attention ----------------
// smem layout (floats)
#define OFF_QT 0
#define OFF_KV (512*66)                 // 33792
#define OFF_SS (OFF_KV + 64*128)        // 41984
#define SMEM_FLOATS (OFF_SS + 64*65)    // 46144  -> 184576 bytes
// grid: (SEQ/TQ, BATCH); block 512
__global__ __launch_bounds__(512, 1) void attn_kernel(float* __restrict__ out)
{
    extern __shared__ float sm[];
    float* sQT = sm + OFF_QT;   // [512][66]  transposed, pre-scaled Q
    float* sKV = sm + OFF_KV;   // [64][128]  K/V h-chunk
    float* sS  = sm + OFF_SS;   // [64][65]   scores -> probs

    const int b    = blockIdx.y;
    const int q0   = blockIdx.x * TQ;
    const int tid  = threadIdx.x;
    const int wid  = tid >> 5;   // 0..15  (owns k-rows in score phase, q-rows in softmax/PV)
    const int lane = tid & 31;

    // ---- load Q tile, transpose into sQT, fold in 1/sqrt(H) ----
    const float* Qg = g_Q + (size_t)(b*SEQ + q0) * HID;
    #pragma unroll
    for (int r = 0; r < 16; r++) {
        int idx = r*512 + tid;          // float4 id 0..8191
        int q  = idx >> 7;              // 128 float4 per row
        int h4 = idx & 127;
        float4 v = *(const float4*)&Qg[(size_t)q*HID + h4*4];
        int hb = h4*4;
        sQT[(hb+0)*66 + q] = v.x * RSCALE;
        sQT[(hb+1)*66 + q] = v.y * RSCALE;
        sQT[(hb+2)*66 + q] = v.z * RSCALE;
        sQT[(hb+3)*66 + q] = v.w * RSCALE;
    }

    float acc[4][16];
    #pragma unroll
    for (int i = 0; i < 4; i++)
        #pragma unroll
        for (int j = 0; j < 16; j++) acc[i][j] = 0.0f;

    float mrow[4], lrow[4];
    #pragma unroll
    for (int i = 0; i < 4; i++) { mrow[i] = -1e30f; lrow[i] = 0.0f; }

    const float* Kg_base = g_K + (size_t)b*SEQ*HID;
    const float* Vg_base = g_V + (size_t)b*SEQ*HID;

    for (int kt = 0; kt < SEQ/TK; kt++) {
        // ================= scores: sc[i][j] = K[wid*4+i] . Qs[2*lane+j] =================
        float sc[4][2];
        #pragma unroll
        for (int i = 0; i < 4; i++) { sc[i][0] = 0.0f; sc[i][1] = 0.0f; }

        const float* Kg = Kg_base + (size_t)kt*TK*HID;
        #pragma unroll
        for (int hc = 0; hc < 4; hc++) {
            __syncthreads();    // previous consumers of sKV done
            #pragma unroll
            for (int r = 0; r < 4; r++) {
                int idx = r*512 + tid;         // 2048 float4
                int key = idx >> 5, h4 = idx & 31;
                *(float4*)&sKV[key*128 + h4*4] =
                    *(const float4*)&Kg[(size_t)key*HID + hc*128 + h4*4];
            }
            __syncthreads();
            const float* qp = &sQT[(hc*128)*66 + 2*lane];
            const float* kp = &sKV[(wid*4)*128];
            #pragma unroll 8
            for (int h = 0; h < 128; h++) {
                float2 qv = *(const float2*)&qp[h*66];
                float k0 = kp[h];
                float k1 = kp[128 + h];
                float k2 = kp[256 + h];
                float k3 = kp[384 + h];
                sc[0][0] += k0*qv.x; sc[0][1] += k0*qv.y;
                sc[1][0] += k1*qv.x; sc[1][1] += k1*qv.y;
                sc[2][0] += k2*qv.x; sc[2][1] += k2*qv.y;
                sc[3][0] += k3*qv.x; sc[3][1] += k3*qv.y;
            }
        }
        // scatter scores into sS[q][k]
        #pragma unroll
        for (int i = 0; i < 4; i++) {
            sS[(2*lane+0)*65 + wid*4 + i] = sc[i][0];
            sS[(2*lane+1)*65 + wid*4 + i] = sc[i][1];
        }
        __syncthreads();

        // ================= online softmax: warp wid owns rows wid*4..+3 =================
        float corr[4];
        #pragma unroll
        for (int rr = 0; rr < 4; rr++) {
            int q = wid*4 + rr;
            float a0 = sS[q*65 + 2*lane];
            float a1 = sS[q*65 + 2*lane + 1];
            float mx = fmaxf(a0, a1);
            #pragma unroll
            for (int o = 16; o > 0; o >>= 1)
                mx = fmaxf(mx, __shfl_xor_sync(0xffffffffu, mx, o));
            float mnew = fmaxf(mrow[rr], mx);
            float p0 = __expf(a0 - mnew);
            float p1 = __expf(a1 - mnew);
            float s = p0 + p1;
            #pragma unroll
            for (int o = 16; o > 0; o >>= 1)
                s += __shfl_xor_sync(0xffffffffu, s, o);
            float c = __expf(mrow[rr] - mnew);
            corr[rr] = c;
            lrow[rr] = lrow[rr]*c + s;
            mrow[rr] = mnew;
            sS[q*65 + 2*lane]     = p0;
            sS[q*65 + 2*lane + 1] = p1;
        }
        #pragma unroll
        for (int i = 0; i < 4; i++)
            #pragma unroll
            for (int j = 0; j < 16; j++) acc[i][j] *= corr[i];

        // ================= PV: acc[i][hc*4+c] += P[wid*4+i][k] * V[k][h] =================
        const float* Vg = Vg_base + (size_t)kt*TK*HID;
        #pragma unroll
        for (int hc = 0; hc < 4; hc++) {
            __syncthreads();
            #pragma unroll
            for (int r = 0; r < 4; r++) {
                int idx = r*512 + tid;
                int key = idx >> 5, h4 = idx & 31;
                *(float4*)&sKV[key*128 + h4*4] =
                    *(const float4*)&Vg[(size_t)key*HID + hc*128 + h4*4];
            }
            __syncthreads();
            const float* pp = &sS[(wid*4)*65];
            #pragma unroll 4
            for (int k = 0; k < 64; k++) {
                float4 vv = *(const float4*)&sKV[k*128 + lane*4];
                float p0 = pp[k];
                float p1 = pp[65  + k];
                float p2 = pp[130 + k];
                float p3 = pp[195 + k];
                acc[0][hc*4+0] += p0*vv.x; acc[0][hc*4+1] += p0*vv.y;
                acc[0][hc*4+2] += p0*vv.z; acc[0][hc*4+3] += p0*vv.w;
                acc[1][hc*4+0] += p1*vv.x; acc[1][hc*4+1] += p1*vv.y;
                acc[1][hc*4+2] += p1*vv.z; acc[1][hc*4+3] += p1*vv.w;
                acc[2][hc*4+0] += p2*vv.x; acc[2][hc*4+1] += p2*vv.y;
                acc[2][hc*4+2] += p2*vv.z; acc[2][hc*4+3] += p2*vv.w;
                acc[3][hc*4+0] += p3*vv.x; acc[3][hc*4+1] += p3*vv.y;
                acc[3][hc*4+2] += p3*vv.z; acc[3][hc*4+3] += p3*vv.w;
            }
        }
    }

    // ================= normalize + store =================
    float invl[4];
    #pragma unroll
    for (int i = 0; i < 4; i++) invl[i] = 1.0f / lrow[i];

    float* Og = out + (size_t)(b*SEQ + q0)*HID;
    #pragma unroll
    for (int i = 0; i < 4; i++) {
        #pragma unroll
        for (int hc = 0; hc < 4; hc++) {
            float4 o;
            o.x = acc[i][hc*4+0]*invl[i];
            o.y = acc[i][hc*4+1]*invl[i];
            o.z = acc[i][hc*4+2]*invl[i];
            o.w = acc[i][hc*4+3]*invl[i];
            *(float4*)&Og[(size_t)(wid*4+i)*HID + hc*128 + lane*4] = o;
        }
    }
}

// ---------------- launcher ----------------
extern "C" void kernel_launch(void* const* d_in, const int* in_sizes, int n_in,
                              void* d_out, int out_size)
{
    const float* x  = (const float*)d_in[0];
    const float* Wq = (const float*)d_in[1];
    const float* bq = (const float*)d_in[2];
    const float* Wk = (const float*)d_in[3];
    const float* bk = (const float*)d_in[4];
    const float* Wv = (const float*)d_in[5];
    const float* bv = (const float*)d_in[6];
    float* out = (float*)d_out;

    cudaFuncSetAttribute(qkv_proj_kernel, cudaFuncAttributeMaxDynamicSharedMemorySize, 64*1024);
    cudaFuncSetAttribute(attn_kernel, cudaFuncAttributeMaxDynamicSharedMemorySize, SMEM_FLOATS*4);

    dim3 pg(M_ROWS/128, HID/128, 3);
    qkv_proj_kernel<<<pg, 256, 64*1024>>>(x, Wq, bq, Wk, bk, Wv, bv);

    dim3 ag(SEQ/TQ, BATCH);
    attn_kernel<<<ag, 512, SMEM_FLOATS*4>>>(out);
}

// round 6
// speedup vs baseline: 8.0844x; 8.0844x over previous
#include <cuda_runtime.h>
#include <cstdint>
#include <math.h>

#define BATCH 8
#define SEQ   4096
#define DIN   64
#define HID   512
#define M_ROWS (BATCH*SEQ)
#define RSCALE 0.044194173824159216f  /* 1/sqrt(512) */

// ---------------- global scratch (allocation-free rule) ----------------
__device__ float g_Q [(size_t)BATCH*SEQ*HID];   // pre-scaled by RSCALE
__device__ float g_K [(size_t)BATCH*SEQ*HID];
__device__ float g_Vt[(size_t)BATCH*HID*SEQ];   // V transposed: [b][h][s]
__device__ float g_P [(size_t)BATCH*SEQ*SEQ];   // unnormalized probs (512 MB)
__device__ float g_rowsum[BATCH*SEQ];

// ======================= helpers =======================
__device__ __forceinline__ uint32_t smem_u32(const void* p) {
    uint32_t a;
    asm("{ .reg .u64 t; cvta.to.shared.u64 t, %1; cvt.u32.u64 %0, t; }" : "=r"(a) : "l"(p));
    return a;
}
__device__ __forceinline__ void cp16(uint32_t saddr, const void* g) {
    asm volatile("cp.async.cg.shared.global [%0], [%1], 16;"
                 :: "r"(saddr), "l"(__cvta_generic_to_global(g)) : "memory");
}
__device__ __forceinline__ uint32_t f2tf32(float f) {
    uint32_t r;
    asm("cvt.rna.tf32.f32 %0, %1;" : "=r"(r) : "f"(f));
    return r;
}
__device__ __forceinline__ void mma_tf32(float* d, const uint32_t* a, const uint32_t* b) {
    asm volatile(
        "mma.sync.aligned.m16n8k8.row.col.f32.tf32.tf32.f32 "
        "{%0,%1,%2,%3}, {%4,%5,%6,%7}, {%8,%9}, {%0,%1,%2,%3};"
        : "+f"(d[0]), "+f"(d[1]), "+f"(d[2]), "+f"(d[3])
        : "r"(a[0]), "r"(a[1]), "r"(a[2]), "r"(a[3]), "r"(b[0]), "r"(b[1]));
}

// ---------------- fused QKV projection (Q scaled, V transposed) ----------------
__global__ __launch_bounds__(256) void qkv_proj_kernel(
    const float* __restrict__ x,
    const float* __restrict__ Wq, const float* __restrict__ bq,
    const float* __restrict__ Wk, const float* __restrict__ bk,
    const float* __restrict__ Wv, const float* __restrict__ bv)
{
    extern __shared__ float psm[];
    float* sX = psm;            // [128][64]
    float* sW = psm + 128*64;   // [64][128]

    const float* Wsel; const float* bsel;
    if (blockIdx.z == 0)      { Wsel = Wq; bsel = bq; }
    else if (blockIdx.z == 1) { Wsel = Wk; bsel = bk; }
    else                      { Wsel = Wv; bsel = bv; }

    const int row0 = blockIdx.x * 128;
    const int col0 = blockIdx.y * 128;
    const int tid  = threadIdx.x;

    #pragma unroll
    for (int i = 0; i < 8; i++) {
        int idx = i*256 + tid;
        int r = idx >> 4, c4 = idx & 15;
        *(float4*)&sX[r*64 + c4*4] = *(const float4*)&x[(size_t)(row0+r)*DIN + c4*4];
    }
    #pragma unroll
    for (int i = 0; i < 8; i++) {
        int idx = i*256 + tid;
        int r = idx >> 5, c4 = idx & 31;
        *(float4*)&sW[r*128 + c4*4] = *(const float4*)&Wsel[(size_t)r*HID + col0 + c4*4];
    }
    __syncthreads();

    const int ty = tid >> 4, tx = tid & 15;
    float acc[8][8];
    #pragma unroll
    for (int i = 0; i < 8; i++)
        #pragma unroll
        for (int j = 0; j < 8; j++) acc[i][j] = 0.0f;

    #pragma unroll 8
    for (int k = 0; k < 64; k++) {
        float xr[8];
        #pragma unroll
        for (int i = 0; i < 8; i++) xr[i] = sX[(ty*8+i)*64 + k];
        float4 w0 = *(const float4*)&sW[k*128 + tx*8];
        float4 w1 = *(const float4*)&sW[k*128 + tx*8 + 4];
        #pragma unroll
        for (int i = 0; i < 8; i++) {
            acc[i][0] += xr[i]*w0.x; acc[i][1] += xr[i]*w0.y;
            acc[i][2] += xr[i]*w0.z; acc[i][3] += xr[i]*w0.w;
            acc[i][4] += xr[i]*w1.x; acc[i][5] += xr[i]*w1.y;
            acc[i][6] += xr[i]*w1.z; acc[i][7] += xr[i]*w1.w;
        }
    }

    float bb[8];
    #pragma unroll
    for (int j = 0; j < 8; j++) bb[j] = __ldg(&bsel[col0 + tx*8 + j]);

    if (blockIdx.z == 2) {
        #pragma unroll
        for (int i = 0; i < 8; i++) {
            int row = row0 + ty*8 + i;
            int bb_i = row >> 12, s = row & (SEQ-1);
            #pragma unroll
            for (int j = 0; j < 8; j++) {
                int col = col0 + tx*8 + j;
                g_Vt[((size_t)bb_i*HID + col)*SEQ + s] = acc[i][j] + bb[j];
            }
        }
    } else {
        float* osel = (blockIdx.z == 0) ? g_Q : g_K;
        float scale = (blockIdx.z == 0) ? RSCALE : 1.0f;
        #pragma unroll
        for (int i = 0; i < 8; i++) {
            float4 o0, o1;
            o0.x = (acc[i][0]+bb[0])*scale; o0.y = (acc[i][1]+bb[1])*scale;
            o0.z = (acc[i][2]+bb[2])*scale; o0.w = (acc[i][3]+bb[3])*scale;
            o1.x = (acc[i][4]+bb[4])*scale; o1.y = (acc[i][5]+bb[5])*scale;
            o1.z = (acc[i][6]+bb[6])*scale; o1.w = (acc[i][7]+bb[7])*scale;
            size_t base = (size_t)(row0 + ty*8 + i)*HID + col0 + tx*8;
            *(float4*)&osel[base]     = o0;
            *(float4*)&osel[base + 4] = o1;
        }
    }
}

// ---------------- rowsum zero ----------------
__global__ void zero_rowsum_kernel() {
    int i = blockIdx.x*256 + threadIdx.x;
    if (i < BATCH*SEQ) g_rowsum[i] = 0.0f;
}

// ======================= tf32 mma.sync GEMM =======================
// C[128,128] per CTA; 8 warps as 2(M) x 4(N); warp tile 64x32.
// K chunked by 32, 2-stage cp.async pipeline, smem rows padded to 36 floats.
// mode 0: C = exp(A.B^T), atomicAdd row sums   (P = exp(QK^T))
// mode 1: C = (A.B^T) / rowsum                 (O = P.V^T / l)
#define KC 32
#define ROWPAD 36
#define TILE_FLOATS (128*ROWPAD)                 // 4608 floats per matrix
#define STAGE_FLOATS (2*TILE_FLOATS)             // A + B
#define SMEM_GEMM (2*STAGE_FLOATS*4)             // 73728 bytes

__global__ __launch_bounds__(256, 2) void gemm_tf32_kernel(
    const float* __restrict__ Abase, const float* __restrict__ Bbase,
    float* __restrict__ Cbase,
    int Kdim, size_t aBatch, size_t bBatch, size_t cBatch, int cld, int mode)
{
    extern __shared__ float sm[];
    const int tid  = threadIdx.x;
    const int wid  = tid >> 5, lane = tid & 31;
    const int warp_m = wid >> 2, warp_n = wid & 3;
    const int g = lane >> 2, tig = lane & 3;
    const int b = blockIdx.z, mt = blockIdx.y, nt = blockIdx.x;

    const float* A = Abase + (size_t)b*aBatch + (size_t)mt*128*Kdim;
    const float* B = Bbase + (size_t)b*bBatch + (size_t)nt*128*Kdim;

    const uint32_t smem_base = smem_u32(sm);
    const int ldrow = tid >> 3, ldf4 = tid & 7;   // each thread: 4 rows apart x 16B

    float acc[4][4][4];
    #pragma unroll
    for (int i = 0; i < 4; i++)
        #pragma unroll
        for (int j = 0; j < 4; j++)
            #pragma unroll
            for (int v = 0; v < 4; v++) acc[i][j][v] = 0.0f;

    const int NCH = Kdim / KC;

    // ---- prologue: load chunk 0 into stage 0 ----
    {
        const float* Ak = A + 0*KC;
        const float* Bk = B + 0*KC;
        uint32_t sA = smem_base;                       // stage 0
        uint32_t sB = smem_base + TILE_FLOATS*4;
        #pragma unroll
        for (int i = 0; i < 4; i++) {
            int r = ldrow + i*32;
            cp16(sA + (r*ROWPAD + ldf4*4)*4, Ak + (size_t)r*Kdim + ldf4*4);
            cp16(sB + (r*ROWPAD + ldf4*4)*4, Bk + (size_t)r*Kdim + ldf4*4);
        }
        asm volatile("cp.async.commit_group;" ::: "memory");
    }

    for (int c = 0; c < NCH; ++c) {
        // ---- prefetch chunk c+1 into other stage ----
        if (c + 1 < NCH) {
            const int st = (c+1) & 1;
            const float* Ak = A + (c+1)*KC;
            const float* Bk = B + (c+1)*KC;
            uint32_t sA = smem_base + st*STAGE_FLOATS*4;
            uint32_t sB = sA + TILE_FLOATS*4;
            #pragma unroll
            for (int i = 0; i < 4; i++) {
                int r = ldrow + i*32;
                cp16(sA + (r*ROWPAD + ldf4*4)*4, Ak + (size_t)r*Kdim + ldf4*4);
                cp16(sB + (r*ROWPAD + ldf4*4)*4, Bk + (size_t)r*Kdim + ldf4*4);
            }
            asm volatile("cp.async.commit_group;" ::: "memory");
            asm volatile("cp.async.wait_group 1;" ::: "memory");
        } else {
            asm volatile("cp.async.wait_group 0;" ::: "memory");
        }
        __syncthreads();

        // ---- compute on stage c&1 ----
        const float* sA = sm + (c & 1)*STAGE_FLOATS;
        const float* sB = sA + TILE_FLOATS;
        const float* sAw = sA + (warp_m*64 + g)*ROWPAD;
        const float* sBw = sB + (warp_n*32 + g)*ROWPAD;

        #pragma unroll
        for (int kk = 0; kk < 4; kk++) {
            const int k0 = kk*8 + tig;
            uint32_t af[4][4];
            #pragma unroll
            for (int am = 0; am < 4; am++) {
                const float* p = sAw + am*16*ROWPAD;
                af[am][0] = f2tf32(p[k0]);
                af[am][1] = f2tf32(p[8*ROWPAD + k0]);
                af[am][2] = f2tf32(p[k0 + 4]);
                af[am][3] = f2tf32(p[8*ROWPAD + k0 + 4]);
            }
            uint32_t bf[4][2];
            #pragma unroll
            for (int bn = 0; bn < 4; bn++) {
                const float* p = sBw + bn*8*ROWPAD;
                bf[bn][0] = f2tf32(p[k0]);
                bf[bn][1] = f2tf32(p[k0 + 4]);
            }
            #pragma unroll
            for (int am = 0; am < 4; am++)
                #pragma unroll
                for (int bn = 0; bn < 4; bn++)
                    mma_tf32(acc[am][bn], af[am], bf[bn]);
        }
        __syncthreads();
    }

    // ================= epilogue =================
    #pragma unroll
    for (int am = 0; am < 4; am++) {
        const int r0 = mt*128 + warp_m*64 + am*16 + g;   // row within batch
        const int r1 = r0 + 8;
        if (mode == 0) {
            float s0 = 0.0f, s1 = 0.0f;
            #pragma unroll
            for (int bn = 0; bn < 4; bn++) {
                const int col = nt*128 + warp_n*32 + bn*8 + 2*tig;
                float e0 = __expf(acc[am][bn][0]);
                float e1 = __expf(acc[am][bn][1]);
                float e2 = __expf(acc[am][bn][2]);
                float e3 = __expf(acc[am][bn][3]);
                s0 += e0 + e1; s1 += e2 + e3;
                float2 o0; o0.x = e0; o0.y = e1;
                float2 o1; o1.x = e2; o1.y = e3;
                *(float2*)(Cbase + (size_t)b*cBatch + (size_t)r0*cld + col) = o0;
                *(float2*)(Cbase + (size_t)b*cBatch + (size_t)r1*cld + col) = o1;
            }
            // reduce over the 4 lanes covering this row (tig group)
            s0 += __shfl_xor_sync(0xffffffffu, s0, 1);
            s0 += __shfl_xor_sync(0xffffffffu, s0, 2);
            s1 += __shfl_xor_sync(0xffffffffu, s1, 1);
            s1 += __shfl_xor_sync(0xffffffffu, s1, 2);
            if (tig == 0) {
                atomicAdd(&g_rowsum[b*SEQ + r0], s0);
                atomicAdd(&g_rowsum[b*SEQ + r1], s1);
            }
        } else {
            float inv0 = 1.0f / g_rowsum[b*SEQ + r0];
            float inv1 = 1.0f / g_rowsum[b*SEQ + r1];
            #pragma unroll
            for (int bn = 0; bn < 4; bn++) {
                const int col = nt*128 + warp_n*32 + bn*8 + 2*tig;
                float2 o0; o0.x = acc[am][bn][0]*inv0; o0.y = acc[am][bn][1]*inv0;
                float2 o1; o1.x = acc[am][bn][2]*inv1; o1.y = acc[am][bn][3]*inv1;
                *(float2*)(Cbase + (size_t)b*cBatch + (size_t)r0*cld + col) = o0;
                *(float2*)(Cbase + (size_t)b*cBatch + (size_t)r1*cld + col) = o1;
            }
        }
    }
}

// ---------------- launcher ----------------
extern "C" void kernel_launch(void* const* d_in, const int* in_sizes, int n_in,
                              void* d_out, int out_size)
{
    const float* x  = (const float*)d_in[0];
    const float* Wq = (const float*)d_in[1];
    const float* bq = (const float*)d_in[2];
    const float* Wk = (const float*)d_in[3];
    const float* bk = (const float*)d_in[4];
    const float* Wv = (const float*)d_in[5];
    const float* bv = (const float*)d_in[6];
    float* out = (float*)d_out;

    cudaFuncSetAttribute(qkv_proj_kernel, cudaFuncAttributeMaxDynamicSharedMemorySize, 64*1024);
    cudaFuncSetAttribute(gemm_tf32_kernel, cudaFuncAttributeMaxDynamicSharedMemorySize, SMEM_GEMM);

    float *g_Q_p, *g_K_p, *g_Vt_p, *g_P_p;
    cudaGetSymbolAddress((void**)&g_Q_p,  g_Q);
    cudaGetSymbolAddress((void**)&g_K_p,  g_K);
    cudaGetSymbolAddress((void**)&g_Vt_p, g_Vt);
    cudaGetSymbolAddress((void**)&g_P_p,  g_P);

    // 1) QKV projections (Q pre-scaled, V transposed)
    dim3 pg(M_ROWS/128, HID/128, 3);
    qkv_proj_kernel<<<pg, 256, 64*1024>>>(x, Wq, bq, Wk, bk, Wv, bv);

    // 2) zero row sums
    zero_rowsum_kernel<<<(BATCH*SEQ + 255)/256, 256>>>();

    // 3) P = exp(Q.K^T) (scale folded into Q), rowsum accumulated
    dim3 sg(SEQ/128, SEQ/128, BATCH);   // (32, 32, 8)
    gemm_tf32_kernel<<<sg, 256, SMEM_GEMM>>>(
        g_Q_p, g_K_p, g_P_p,
        HID, (size_t)SEQ*HID, (size_t)SEQ*HID, (size_t)SEQ*SEQ, SEQ, 0);

    // 4) O = (P.Vt^T) / rowsum
    dim3 og(HID/128, SEQ/128, BATCH);   // (4, 32, 8)
    gemm_tf32_kernel<<<og, 256, SMEM_GEMM>>>(
        g_P_p, g_Vt_p, out,
        SEQ, (size_t)SEQ*SEQ, (size_t)HID*SEQ, (size_t)SEQ*HID, HID, 1);
}

// round 7
// speedup vs baseline: 8.5820x; 1.0615x over previous
#include <cuda_runtime.h>
#include <cstdint>
#include <math.h>

#define BATCH 8
#define SEQ   4096
#define DIN   64
#define HID   512
#define M_ROWS (BATCH*SEQ)
#define RSCALE 0.044194173824159216f  /* 1/sqrt(512) */

// ---------------- global scratch (allocation-free rule) ----------------
__device__ float g_Q [(size_t)BATCH*SEQ*HID];   // pre-scaled by RSCALE, tf32-rounded
__device__ float g_K [(size_t)BATCH*SEQ*HID];   // tf32-rounded
__device__ float g_Vt[(size_t)BATCH*HID*SEQ];   // V transposed [b][h][s], tf32-rounded
__device__ float g_P [(size_t)BATCH*SEQ*SEQ];   // unnormalized probs, tf32-rounded
__device__ float g_rowsum[BATCH*SEQ];

// ======================= helpers =======================
__device__ __forceinline__ uint32_t smem_u32(const void* p) {
    uint32_t a;
    asm("{ .reg .u64 t; cvta.to.shared.u64 t, %1; cvt.u32.u64 %0, t; }" : "=r"(a) : "l"(p));
    return a;
}
__device__ __forceinline__ void cp16(uint32_t saddr, const void* g) {
    asm volatile("cp.async.cg.shared.global [%0], [%1], 16;"
                 :: "r"(saddr), "l"(__cvta_generic_to_global(g)) : "memory");
}
__device__ __forceinline__ float f2tf32f(float f) {
    uint32_t r;
    asm("cvt.rna.tf32.f32 %0, %1;" : "=r"(r) : "f"(f));
    return __uint_as_float(r);
}
__device__ __forceinline__ void mma_tf32(float* d, const uint32_t* a, const uint32_t* b) {
    asm volatile(
        "mma.sync.aligned.m16n8k8.row.col.f32.tf32.tf32.f32 "
        "{%0,%1,%2,%3}, {%4,%5,%6,%7}, {%8,%9}, {%0,%1,%2,%3};"
        : "+f"(d[0]), "+f"(d[1]), "+f"(d[2]), "+f"(d[3])
        : "r"(a[0]), "r"(a[1]), "r"(a[2]), "r"(a[3]), "r"(b[0]), "r"(b[1]));
}

// ---------------- fused QKV projection (Q scaled, V transposed, tf32-rounded) ----------------
__global__ __launch_bounds__(256) void qkv_proj_kernel(
    const float* __restrict__ x,
    const float* __restrict__ Wq, const float* __restrict__ bq,
    const float* __restrict__ Wk, const float* __restrict__ bk,
    const float* __restrict__ Wv, const float* __restrict__ bv)
{
    extern __shared__ float psm[];
    float* sX = psm;            // [128][64]
    float* sW = psm + 128*64;   // [64][128]

    const float* Wsel; const float* bsel;
    if (blockIdx.z == 0)      { Wsel = Wq; bsel = bq; }
    else if (blockIdx.z == 1) { Wsel = Wk; bsel = bk; }
    else                      { Wsel = Wv; bsel = bv; }

    const int row0 = blockIdx.x * 128;
    const int col0 = blockIdx.y * 128;
    const int tid  = threadIdx.x;

    #pragma unroll
    for (int i = 0; i < 8; i++) {
        int idx = i*256 + tid;
        int r = idx >> 4, c4 = idx & 15;
        *(float4*)&sX[r*64 + c4*4] = *(const float4*)&x[(size_t)(row0+r)*DIN + c4*4];
    }
    #pragma unroll
    for (int i = 0; i < 8; i++) {
        int idx = i*256 + tid;
        int r = idx >> 5, c4 = idx & 31;
        *(float4*)&sW[r*128 + c4*4] = *(const float4*)&Wsel[(size_t)r*HID + col0 + c4*4];
    }
    __syncthreads();

    const int ty = tid >> 4, tx = tid & 15;
    float acc[8][8];
    #pragma unroll
    for (int i = 0; i < 8; i++)
        #pragma unroll
        for (int j = 0; j < 8; j++) acc[i][j] = 0.0f;

    #pragma unroll 8
    for (int k = 0; k < 64; k++) {
        float xr[8];
        #pragma unroll
        for (int i = 0; i < 8; i++) xr[i] = sX[(ty*8+i)*64 + k];
        float4 w0 = *(const float4*)&sW[k*128 + tx*8];
        float4 w1 = *(const float4*)&sW[k*128 + tx*8 + 4];
        #pragma unroll
        for (int i = 0; i < 8; i++) {
            acc[i][0] += xr[i]*w0.x; acc[i][1] += xr[i]*w0.y;
            acc[i][2] += xr[i]*w0.z; acc[i][3] += xr[i]*w0.w;
            acc[i][4] += xr[i]*w1.x; acc[i][5] += xr[i]*w1.y;
            acc[i][6] += xr[i]*w1.z; acc[i][7] += xr[i]*w1.w;
        }
    }

    float bb[8];
    #pragma unroll
    for (int j = 0; j < 8; j++) bb[j] = __ldg(&bsel[col0 + tx*8 + j]);

    if (blockIdx.z == 2) {
        // V transposed: per (thread, col j) the 8 row values are contiguous in s.
        int row_base = row0 + ty*8;
        int bb_i = row_base >> 12, s0 = row_base & (SEQ-1);
        #pragma unroll
        for (int j = 0; j < 8; j++) {
            int col = col0 + tx*8 + j;
            float* dst = &g_Vt[((size_t)bb_i*HID + col)*SEQ + s0];
            float4 o0, o1;
            o0.x = f2tf32f(acc[0][j]+bb[j]); o0.y = f2tf32f(acc[1][j]+bb[j]);
            o0.z = f2tf32f(acc[2][j]+bb[j]); o0.w = f2tf32f(acc[3][j]+bb[j]);
            o1.x = f2tf32f(acc[4][j]+bb[j]); o1.y = f2tf32f(acc[5][j]+bb[j]);
            o1.z = f2tf32f(acc[6][j]+bb[j]); o1.w = f2tf32f(acc[7][j]+bb[j]);
            *(float4*)dst       = o0;
            *(float4*)(dst + 4) = o1;
        }
    } else {
        float* osel = (blockIdx.z == 0) ? g_Q : g_K;
        float scale = (blockIdx.z == 0) ? RSCALE : 1.0f;
        #pragma unroll
        for (int i = 0; i < 8; i++) {
            float4 o0, o1;
            o0.x = f2tf32f((acc[i][0]+bb[0])*scale); o0.y = f2tf32f((acc[i][1]+bb[1])*scale);
            o0.z = f2tf32f((acc[i][2]+bb[2])*scale); o0.w = f2tf32f((acc[i][3]+bb[3])*scale);
            o1.x = f2tf32f((acc[i][4]+bb[4])*scale); o1.y = f2tf32f((acc[i][5]+bb[5])*scale);
            o1.z = f2tf32f((acc[i][6]+bb[6])*scale); o1.w = f2tf32f((acc[i][7]+bb[7])*scale);
            size_t base = (size_t)(row0 + ty*8 + i)*HID + col0 + tx*8;
            *(float4*)&osel[base]     = o0;
            *(float4*)&osel[base + 4] = o1;
        }
    }
}

// ---------------- rowsum zero ----------------
__global__ void zero_rowsum_kernel() {
    int i = blockIdx.x*256 + threadIdx.x;
    if (i < BATCH*SEQ) g_rowsum[i] = 0.0f;
}

// ======================= tf32 mma.sync GEMM (inputs pre-rounded) =======================
// C[128,128] per CTA; 8 warps as 2(M) x 4(N); warp tile 64x32.
// K chunked by 32, 2-stage cp.async pipeline, smem rows padded to 36 floats.
// mode 0: C = exp(A.B^T) tf32-rounded, atomicAdd row sums   (P = exp(QK^T))
// mode 1: C = (A.B^T) / rowsum                              (O = P.V^T / l)
#define KC 32
#define ROWPAD 36
#define TILE_FLOATS (128*ROWPAD)
#define STAGE_FLOATS (2*TILE_FLOATS)
#define SMEM_GEMM (2*STAGE_FLOATS*4)             // 73728 bytes

__global__ __launch_bounds__(256, 2) void gemm_tf32_kernel(
    const float* __restrict__ Abase, const float* __restrict__ Bbase,
    float* __restrict__ Cbase,
    int Kdim, size_t aBatch, size_t bBatch, size_t cBatch, int cld, int mode)
{
    extern __shared__ float sm[];
    const int tid  = threadIdx.x;
    const int wid  = tid >> 5, lane = tid & 31;
    const int warp_m = wid >> 2, warp_n = wid & 3;
    const int g = lane >> 2, tig = lane & 3;
    const int b = blockIdx.z, mt = blockIdx.y, nt = blockIdx.x;

    const float* A = Abase + (size_t)b*aBatch + (size_t)mt*128*Kdim;
    const float* B = Bbase + (size_t)b*bBatch + (size_t)nt*128*Kdim;

    const uint32_t smem_base = smem_u32(sm);
    const int ldrow = tid >> 3, ldf4 = tid & 7;

    float acc[4][4][4];
    #pragma unroll
    for (int i = 0; i < 4; i++)
        #pragma unroll
        for (int j = 0; j < 4; j++)
            #pragma unroll
            for (int v = 0; v < 4; v++) acc[i][j][v] = 0.0f;

    const int NCH = Kdim / KC;

    // ---- prologue: chunk 0 -> stage 0 ----
    {
        uint32_t sA = smem_base;
        uint32_t sB = smem_base + TILE_FLOATS*4;
        #pragma unroll
        for (int i = 0; i < 4; i++) {
            int r = ldrow + i*32;
            cp16(sA + (r*ROWPAD + ldf4*4)*4, A + (size_t)r*Kdim + ldf4*4);
            cp16(sB + (r*ROWPAD + ldf4*4)*4, B + (size_t)r*Kdim + ldf4*4);
        }
        asm volatile("cp.async.commit_group;" ::: "memory");
    }

    for (int c = 0; c < NCH; ++c) {
        if (c + 1 < NCH) {
            const int st = (c+1) & 1;
            const float* Ak = A + (c+1)*KC;
            const float* Bk = B + (c+1)*KC;
            uint32_t sA = smem_base + st*STAGE_FLOATS*4;
            uint32_t sB = sA + TILE_FLOATS*4;
            #pragma unroll
            for (int i = 0; i < 4; i++) {
                int r = ldrow + i*32;
                cp16(sA + (r*ROWPAD + ldf4*4)*4, Ak + (size_t)r*Kdim + ldf4*4);
                cp16(sB + (r*ROWPAD + ldf4*4)*4, Bk + (size_t)r*Kdim + ldf4*4);
            }
            asm volatile("cp.async.commit_group;" ::: "memory");
            asm volatile("cp.async.wait_group 1;" ::: "memory");
        } else {
            asm volatile("cp.async.wait_group 0;" ::: "memory");
        }
        __syncthreads();

        const float* sA = sm + (c & 1)*STAGE_FLOATS;
        const float* sB = sA + TILE_FLOATS;
        const uint32_t* sAw = (const uint32_t*)(sA + (warp_m*64 + g)*ROWPAD);
        const uint32_t* sBw = (const uint32_t*)(sB + (warp_n*32 + g)*ROWPAD);

        #pragma unroll
        for (int kk = 0; kk < 4; kk++) {
            const int k0 = kk*8 + tig;
            uint32_t af[4][4];
            #pragma unroll
            for (int am = 0; am < 4; am++) {
                const uint32_t* p = sAw + am*16*ROWPAD;
                af[am][0] = p[k0];
                af[am][1] = p[8*ROWPAD + k0];
                af[am][2] = p[k0 + 4];
                af[am][3] = p[8*ROWPAD + k0 + 4];
            }
            uint32_t bf[4][2];
            #pragma unroll
            for (int bn = 0; bn < 4; bn++) {
                const uint32_t* p = sBw + bn*8*ROWPAD;
                bf[bn][0] = p[k0];
                bf[bn][1] = p[k0 + 4];
            }
            #pragma unroll
            for (int am = 0; am < 4; am++)
                #pragma unroll
                for (int bn = 0; bn < 4; bn++)
                    mma_tf32(acc[am][bn], af[am], bf[bn]);
        }
        __syncthreads();
    }

    // ================= epilogue =================
    #pragma unroll
    for (int am = 0; am < 4; am++) {
        const int r0 = mt*128 + warp_m*64 + am*16 + g;
        const int r1 = r0 + 8;
        if (mode == 0) {
            float s0 = 0.0f, s1 = 0.0f;
            #pragma unroll
            for (int bn = 0; bn < 4; bn++) {
                const int col = nt*128 + warp_n*32 + bn*8 + 2*tig;
                float e0 = f2tf32f(__expf(acc[am][bn][0]));
                float e1 = f2tf32f(__expf(acc[am][bn][1]));
                float e2 = f2tf32f(__expf(acc[am][bn][2]));
                float e3 = f2tf32f(__expf(acc[am][bn][3]));
                s0 += e0 + e1; s1 += e2 + e3;
                float2 o0; o0.x = e0; o0.y = e1;
                float2 o1; o1.x = e2; o1.y = e3;
                *(float2*)(Cbase + (size_t)b*cBatch + (size_t)r0*cld + col) = o0;
                *(float2*)(Cbase + (size_t)b*cBatch + (size_t)r1*cld + col) = o1;
            }
            s0 += __shfl_xor_sync(0xffffffffu, s0, 1);
            s0 += __shfl_xor_sync(0xffffffffu, s0, 2);
            s1 += __shfl_xor_sync(0xffffffffu, s1, 1);
            s1 += __shfl_xor_sync(0xffffffffu, s1, 2);
            if (tig == 0) {
                atomicAdd(&g_rowsum[b*SEQ + r0], s0);
                atomicAdd(&g_rowsum[b*SEQ + r1], s1);
            }
        } else {
            float inv0 = 1.0f / g_rowsum[b*SEQ + r0];
            float inv1 = 1.0f / g_rowsum[b*SEQ + r1];
            #pragma unroll
            for (int bn = 0; bn < 4; bn++) {
                const int col = nt*128 + warp_n*32 + bn*8 + 2*tig;
                float2 o0; o0.x = acc[am][bn][0]*inv0; o0.y = acc[am][bn][1]*inv0;
                float2 o1; o1.x = acc[am][bn][2]*inv1; o1.y = acc[am][bn][3]*inv1;
                *(float2*)(Cbase + (size_t)b*cBatch + (size_t)r0*cld + col) = o0;
                *(float2*)(Cbase + (size_t)b*cBatch + (size_t)r1*cld + col) = o1;
            }
        }
    }
}

// ---------------- launcher ----------------
extern "C" void kernel_launch(void* const* d_in, const int* in_sizes, int n_in,
                              void* d_out, int out_size)
{
    const float* x  = (const float*)d_in[0];
    const float* Wq = (const float*)d_in[1];
    const float* bq = (const float*)d_in[2];
    const float* Wk = (const float*)d_in[3];
    const float* bk = (const float*)d_in[4];
    const float* Wv = (const float*)d_in[5];
    const float* bv = (const float*)d_in[6];
    float* out = (float*)d_out;

    cudaFuncSetAttribute(qkv_proj_kernel, cudaFuncAttributeMaxDynamicSharedMemorySize, 64*1024);
    cudaFuncSetAttribute(gemm_tf32_kernel, cudaFuncAttributeMaxDynamicSharedMemorySize, SMEM_GEMM);

    float *g_Q_p, *g_K_p, *g_Vt_p, *g_P_p;
    cudaGetSymbolAddress((void**)&g_Q_p,  g_Q);
    cudaGetSymbolAddress((void**)&g_K_p,  g_K);
    cudaGetSymbolAddress((void**)&g_Vt_p, g_Vt);
    cudaGetSymbolAddress((void**)&g_P_p,  g_P);

    // 1) QKV projections
    dim3 pg(M_ROWS/128, HID/128, 3);
    qkv_proj_kernel<<<pg, 256, 64*1024>>>(x, Wq, bq, Wk, bk, Wv, bv);

    // 2) zero row sums
    zero_rowsum_kernel<<<(BATCH*SEQ + 255)/256, 256>>>();

    // 3) P = exp(Q.K^T), rowsum accumulated
    dim3 sg(SEQ/128, SEQ/128, BATCH);   // (32, 32, 8)
    gemm_tf32_kernel<<<sg, 256, SMEM_GEMM>>>(
        g_Q_p, g_K_p, g_P_p,
        HID, (size_t)SEQ*HID, (size_t)SEQ*HID, (size_t)SEQ*SEQ, SEQ, 0);

    // 4) O = (P.Vt^T) / rowsum
    dim3 og(HID/128, SEQ/128, BATCH);   // (4, 32, 8)
    gemm_tf32_kernel<<<og, 256, SMEM_GEMM>>>(
        g_P_p, g_Vt_p, out,
        SEQ, (size_t)SEQ*SEQ, (size_t)HID*SEQ, (size_t)SEQ*HID, HID, 1);
}

// round 8
// speedup vs baseline: 9.4500x; 1.1011x over previous
#include <cuda_runtime.h>
#include <cstdint>
#include <math.h>

#define BATCH 8
#define SEQ   4096
#define DIN   64
#define HID   512
#define M_ROWS (BATCH*SEQ)
#define RSCALE 0.044194173824159216f  /* 1/sqrt(512) */

// All K-contiguous operand arrays (Q, K, Vt, P) are stored with columns
// permuted within each 8-group to order [0,4,1,5,2,6,3,7] so mma fragment
// (k, k+4) pairs are adjacent -> float2 fragment loads.
// Dot products are invariant since both GEMM operands share the permutation.

// ---------------- global scratch (allocation-free rule) ----------------
__device__ float g_Q [(size_t)BATCH*SEQ*HID];   // scaled, tf32-rounded, k-perm
__device__ float g_K [(size_t)BATCH*SEQ*HID];   // tf32-rounded, k-perm
__device__ float g_Vt[(size_t)BATCH*HID*SEQ];   // V^T [b][h][s], tf32-rounded, s-perm
__device__ float g_P [(size_t)BATCH*SEQ*SEQ];   // probs, tf32-rounded, s-perm
__device__ float g_rowsum[BATCH*SEQ];

// ======================= helpers =======================
__device__ __forceinline__ uint32_t smem_u32(const void* p) {
    uint32_t a;
    asm("{ .reg .u64 t; cvta.to.shared.u64 t, %1; cvt.u32.u64 %0, t; }" : "=r"(a) : "l"(p));
    return a;
}
__device__ __forceinline__ void cp16(uint32_t saddr, const void* g) {
    asm volatile("cp.async.cg.shared.global [%0], [%1], 16;"
                 :: "r"(saddr), "l"(__cvta_generic_to_global(g)) : "memory");
}
__device__ __forceinline__ float f2tf32f(float f) {
    uint32_t r;
    asm("cvt.rna.tf32.f32 %0, %1;" : "=r"(r) : "f"(f));
    return __uint_as_float(r);
}
__device__ __forceinline__ void mma_tf32(float* d, const uint32_t* a, const uint32_t* b) {
    asm volatile(
        "mma.sync.aligned.m16n8k8.row.col.f32.tf32.tf32.f32 "
        "{%0,%1,%2,%3}, {%4,%5,%6,%7}, {%8,%9}, {%0,%1,%2,%3};"
        : "+f"(d[0]), "+f"(d[1]), "+f"(d[2]), "+f"(d[3])
        : "r"(a[0]), "r"(a[1]), "r"(a[2]), "r"(a[3]), "r"(b[0]), "r"(b[1]));
}

// ---------------- fused QKV projection (writes permuted layouts) ----------------
__global__ __launch_bounds__(256) void qkv_proj_kernel(
    const float* __restrict__ x,
    const float* __restrict__ Wq, const float* __restrict__ bq,
    const float* __restrict__ Wk, const float* __restrict__ bk,
    const float* __restrict__ Wv, const float* __restrict__ bv)
{
    extern __shared__ float psm[];
    float* sX = psm;            // [128][64]
    float* sW = psm + 128*64;   // [64][128]

    const float* Wsel; const float* bsel;
    if (blockIdx.z == 0)      { Wsel = Wq; bsel = bq; }
    else if (blockIdx.z == 1) { Wsel = Wk; bsel = bk; }
    else                      { Wsel = Wv; bsel = bv; }

    const int row0 = blockIdx.x * 128;
    const int col0 = blockIdx.y * 128;
    const int tid  = threadIdx.x;

    #pragma unroll
    for (int i = 0; i < 8; i++) {
        int idx = i*256 + tid;
        int r = idx >> 4, c4 = idx & 15;
        *(float4*)&sX[r*64 + c4*4] = *(const float4*)&x[(size_t)(row0+r)*DIN + c4*4];
    }
    #pragma unroll
    for (int i = 0; i < 8; i++) {
        int idx = i*256 + tid;
        int r = idx >> 5, c4 = idx & 31;
        *(float4*)&sW[r*128 + c4*4] = *(const float4*)&Wsel[(size_t)r*HID + col0 + c4*4];
    }
    __syncthreads();

    const int ty = tid >> 4, tx = tid & 15;
    float acc[8][8];
    #pragma unroll
    for (int i = 0; i < 8; i++)
        #pragma unroll
        for (int j = 0; j < 8; j++) acc[i][j] = 0.0f;

    #pragma unroll 8
    for (int k = 0; k < 64; k++) {
        float xr[8];
        #pragma unroll
        for (int i = 0; i < 8; i++) xr[i] = sX[(ty*8+i)*64 + k];
        float4 w0 = *(const float4*)&sW[k*128 + tx*8];
        float4 w1 = *(const float4*)&sW[k*128 + tx*8 + 4];
        #pragma unroll
        for (int i = 0; i < 8; i++) {
            acc[i][0] += xr[i]*w0.x; acc[i][1] += xr[i]*w0.y;
            acc[i][2] += xr[i]*w0.z; acc[i][3] += xr[i]*w0.w;
            acc[i][4] += xr[i]*w1.x; acc[i][5] += xr[i]*w1.y;
            acc[i][6] += xr[i]*w1.z; acc[i][7] += xr[i]*w1.w;
        }
    }

    float bb[8];
    #pragma unroll
    for (int j = 0; j < 8; j++) bb[j] = __ldg(&bsel[col0 + tx*8 + j]);

    if (blockIdx.z == 2) {
        // V^T: fixed col h -> 8 consecutive s values; write in s-perm order.
        int row_base = row0 + ty*8;
        int bb_i = row_base >> 12, s0 = row_base & (SEQ-1);
        #pragma unroll
        for (int j = 0; j < 8; j++) {
            int col = col0 + tx*8 + j;
            float* dst = &g_Vt[((size_t)bb_i*HID + col)*SEQ + s0];
            float v[8];
            #pragma unroll
            for (int i = 0; i < 8; i++) v[i] = f2tf32f(acc[i][j] + bb[j]);
            float4 o0, o1;
            o0.x = v[0]; o0.y = v[4]; o0.z = v[1]; o0.w = v[5];
            o1.x = v[2]; o1.y = v[6]; o1.z = v[3]; o1.w = v[7];
            *(float4*)dst       = o0;
            *(float4*)(dst + 4) = o1;
        }
    } else {
        float* osel = (blockIdx.z == 0) ? g_Q : g_K;
        float scale = (blockIdx.z == 0) ? RSCALE : 1.0f;
        #pragma unroll
        for (int i = 0; i < 8; i++) {
            float a[8];
            #pragma unroll
            for (int j = 0; j < 8; j++) a[j] = f2tf32f((acc[i][j] + bb[j])*scale);
            float4 o0, o1;
            o0.x = a[0]; o0.y = a[4]; o0.z = a[1]; o0.w = a[5];
            o1.x = a[2]; o1.y = a[6]; o1.z = a[3]; o1.w = a[7];
            size_t base = (size_t)(row0 + ty*8 + i)*HID + col0 + tx*8;
            *(float4*)&osel[base]     = o0;
            *(float4*)&osel[base + 4] = o1;
        }
    }
}

// ---------------- rowsum zero ----------------
__global__ void zero_rowsum_kernel() {
    int i = blockIdx.x*256 + threadIdx.x;
    if (i < BATCH*SEQ) g_rowsum[i] = 0.0f;
}

// ======================= tf32 mma.sync GEMM (k-permuted operands) =======================
// C[128,128] per CTA; 8 warps as 2(M) x 4(N); warp tile 64x32.
// K chunked by 32, 2-stage cp.async pipeline, smem rows padded to 40 floats
// (ROWPAD=40 -> 8g mod 32 distinct per 16-lane phase -> conflict-free float2 loads).
// mode 0: C = exp(A.B^T) tf32-rounded, k-perm stores, atomicAdd row sums
// mode 1: C = (A.B^T) / rowsum, normal layout stores
#define KC 32
#define ROWPAD 40
#define TILE_FLOATS (128*ROWPAD)
#define STAGE_FLOATS (2*TILE_FLOATS)
#define SMEM_GEMM (2*STAGE_FLOATS*4)             // 81920 bytes

__global__ __launch_bounds__(256, 2) void gemm_tf32_kernel(
    const float* __restrict__ Abase, const float* __restrict__ Bbase,
    float* __restrict__ Cbase,
    int Kdim, size_t aBatch, size_t bBatch, size_t cBatch, int cld, int mode)
{
    extern __shared__ float sm[];
    const int tid  = threadIdx.x;
    const int wid  = tid >> 5, lane = tid & 31;
    const int warp_m = wid >> 2, warp_n = wid & 3;
    const int g = lane >> 2, tig = lane & 3;
    const int b = blockIdx.z, mt = blockIdx.y, nt = blockIdx.x;

    const float* A = Abase + (size_t)b*aBatch + (size_t)mt*128*Kdim;
    const float* B = Bbase + (size_t)b*bBatch + (size_t)nt*128*Kdim;

    const uint32_t smem_base = smem_u32(sm);
    const int ldrow = tid >> 3, ldf4 = tid & 7;

    float acc[4][4][4];
    #pragma unroll
    for (int i = 0; i < 4; i++)
        #pragma unroll
        for (int j = 0; j < 4; j++)
            #pragma unroll
            for (int v = 0; v < 4; v++) acc[i][j][v] = 0.0f;

    const int NCH = Kdim / KC;

    // ---- prologue: chunk 0 -> stage 0 ----
    {
        uint32_t sA = smem_base;
        uint32_t sB = smem_base + TILE_FLOATS*4;
        #pragma unroll
        for (int i = 0; i < 4; i++) {
            int r = ldrow + i*32;
            cp16(sA + (r*ROWPAD + ldf4*4)*4, A + (size_t)r*Kdim + ldf4*4);
            cp16(sB + (r*ROWPAD + ldf4*4)*4, B + (size_t)r*Kdim + ldf4*4);
        }
        asm volatile("cp.async.commit_group;" ::: "memory");
    }

    for (int c = 0; c < NCH; ++c) {
        if (c + 1 < NCH) {
            const int st = (c+1) & 1;
            const float* Ak = A + (c+1)*KC;
            const float* Bk = B + (c+1)*KC;
            uint32_t sA = smem_base + st*STAGE_FLOATS*4;
            uint32_t sB = sA + TILE_FLOATS*4;
            #pragma unroll
            for (int i = 0; i < 4; i++) {
                int r = ldrow + i*32;
                cp16(sA + (r*ROWPAD + ldf4*4)*4, Ak + (size_t)r*Kdim + ldf4*4);
                cp16(sB + (r*ROWPAD + ldf4*4)*4, Bk + (size_t)r*Kdim + ldf4*4);
            }
            asm volatile("cp.async.commit_group;" ::: "memory");
            asm volatile("cp.async.wait_group 1;" ::: "memory");
        } else {
            asm volatile("cp.async.wait_group 0;" ::: "memory");
        }
        __syncthreads();

        const float* sA = sm + (c & 1)*STAGE_FLOATS;
        const float* sB = sA + TILE_FLOATS;
        const float* sAw = sA + (warp_m*64 + g)*ROWPAD;
        const float* sBw = sB + (warp_n*32 + g)*ROWPAD;

        #pragma unroll
        for (int kk = 0; kk < 4; kk++) {
            const int kof = kk*8 + 2*tig;   // permuted position of (k0, k0+4)
            uint32_t af[4][4];
            #pragma unroll
            for (int am = 0; am < 4; am++) {
                float2 lo = *(const float2*)(sAw + am*16*ROWPAD + kof);
                float2 hi = *(const float2*)(sAw + am*16*ROWPAD + 8*ROWPAD + kof);
                af[am][0] = __float_as_uint(lo.x);
                af[am][1] = __float_as_uint(hi.x);
                af[am][2] = __float_as_uint(lo.y);
                af[am][3] = __float_as_uint(hi.y);
            }
            uint32_t bf[4][2];
            #pragma unroll
            for (int bn = 0; bn < 4; bn++) {
                float2 bv = *(const float2*)(sBw + bn*8*ROWPAD + kof);
                bf[bn][0] = __float_as_uint(bv.x);
                bf[bn][1] = __float_as_uint(bv.y);
            }
            #pragma unroll
            for (int am = 0; am < 4; am++)
                #pragma unroll
                for (int bn = 0; bn < 4; bn++)
                    mma_tf32(acc[am][bn], af[am], bf[bn]);
        }
        __syncthreads();
    }

    // ================= epilogue =================
    // thread holds C rows (r0, r1=r0+8), cols (c0=2*tig, c0+1) within each bn 8-group
    // permuted position of col c within its 8-group: c<4 ? 2c : 2(c-4)+1
    const int p0 = (tig & 2) ? (4*(tig & 1) + 1) : (4*tig);   // pos of c0; c0+1 at p0+2
    #pragma unroll
    for (int am = 0; am < 4; am++) {
        const int r0 = mt*128 + warp_m*64 + am*16 + g;
        const int r1 = r0 + 8;
        if (mode == 0) {
            float s0 = 0.0f, s1 = 0.0f;
            #pragma unroll
            for (int bn = 0; bn < 4; bn++) {
                const int colbase = nt*128 + warp_n*32 + bn*8;
                float e0 = f2tf32f(__expf(acc[am][bn][0]));
                float e1 = f2tf32f(__expf(acc[am][bn][1]));
                float e2 = f2tf32f(__expf(acc[am][bn][2]));
                float e3 = f2tf32f(__expf(acc[am][bn][3]));
                s0 += e0 + e1; s1 += e2 + e3;
                float* b0 = Cbase + (size_t)b*cBatch + (size_t)r0*cld + colbase;
                float* b1 = Cbase + (size_t)b*cBatch + (size_t)r1*cld + colbase;
                b0[p0] = e0; b0[p0+2] = e1;
                b1[p0] = e2; b1[p0+2] = e3;
            }
            s0 += __shfl_xor_sync(0xffffffffu, s0, 1);
            s0 += __shfl_xor_sync(0xffffffffu, s0, 2);
            s1 += __shfl_xor_sync(0xffffffffu, s1, 1);
            s1 += __shfl_xor_sync(0xffffffffu, s1, 2);
            if (tig == 0) {
                atomicAdd(&g_rowsum[b*SEQ + r0], s0);
                atomicAdd(&g_rowsum[b*SEQ + r1], s1);
            }
        } else {
            float inv0 = 1.0f / g_rowsum[b*SEQ + r0];
            float inv1 = 1.0f / g_rowsum[b*SEQ + r1];
            #pragma unroll
            for (int bn = 0; bn < 4; bn++) {
                const int col = nt*128 + warp_n*32 + bn*8 + 2*tig;
                float2 o0; o0.x = acc[am][bn][0]*inv0; o0.y = acc[am][bn][1]*inv0;
                float2 o1; o1.x = acc[am][bn][2]*inv1; o1.y = acc[am][bn][3]*inv1;
                *(float2*)(Cbase + (size_t)b*cBatch + (size_t)r0*cld + col) = o0;
                *(float2*)(Cbase + (size_t)b*cBatch + (size_t)r1*cld + col) = o1;
            }
        }
    }
}

// ---------------- launcher ----------------
extern "C" void kernel_launch(void* const* d_in, const int* in_sizes, int n_in,
                              void* d_out, int out_size)
{
    const float* x  = (const float*)d_in[0];
    const float* Wq = (const float*)d_in[1];
    const float* bq = (const float*)d_in[2];
    const float* Wk = (const float*)d_in[3];
    const float* bk = (const float*)d_in[4];
    const float* Wv = (const float*)d_in[5];
    const float* bv = (const float*)d_in[6];
    float* out = (float*)d_out;

    cudaFuncSetAttribute(qkv_proj_kernel, cudaFuncAttributeMaxDynamicSharedMemorySize, 64*1024);
    cudaFuncSetAttribute(gemm_tf32_kernel, cudaFuncAttributeMaxDynamicSharedMemorySize, SMEM_GEMM);

    float *g_Q_p, *g_K_p, *g_Vt_p, *g_P_p;
    cudaGetSymbolAddress((void**)&g_Q_p,  g_Q);
    cudaGetSymbolAddress((void**)&g_K_p,  g_K);
    cudaGetSymbolAddress((void**)&g_Vt_p, g_Vt);
    cudaGetSymbolAddress((void**)&g_P_p,  g_P);

    // 1) QKV projections (permuted layouts)
    dim3 pg(M_ROWS/128, HID/128, 3);
    qkv_proj_kernel<<<pg, 256, 64*1024>>>(x, Wq, bq, Wk, bk, Wv, bv);

    // 2) zero row sums
    zero_rowsum_kernel<<<(BATCH*SEQ + 255)/256, 256>>>();

    // 3) P = exp(Q.K^T), rowsum accumulated
    dim3 sg(SEQ/128, SEQ/128, BATCH);   // (32, 32, 8)
    gemm_tf32_kernel<<<sg, 256, SMEM_GEMM>>>(
        g_Q_p, g_K_p, g_P_p,
        HID, (size_t)SEQ*HID, (size_t)SEQ*HID, (size_t)SEQ*SEQ, SEQ, 0);

    // 4) O = (P.Vt^T) / rowsum
    dim3 og(HID/128, SEQ/128, BATCH);   // (4, 32, 8)
    gemm_tf32_kernel<<<og, 256, SMEM_GEMM>>>(
        g_P_p, g_Vt_p, out,
        SEQ, (size_t)SEQ*SEQ, (size_t)HID*SEQ, (size_t)SEQ*HID, HID, 1);
}

// round 9
// speedup vs baseline: 16.4400x; 1.7397x over previous
#include <cuda_runtime.h>
#include <cuda_fp16.h>
#include <cstdint>
#include <math.h>

#define BATCH 8
#define SEQ   4096
#define DIN   64
#define HID   512
#define M_ROWS (BATCH*SEQ)
#define RSCALE 0.044194173824159216f  /* 1/sqrt(512) */

// All K-contiguous fp16 operand arrays (Q, K, Vt, P) are stored with columns
// permuted within each 16-group to order [0,1,8,9, 2,3,10,11, 4,5,12,13, 6,7,14,15]
// so an m16n8k16 fragment piece (k = 2t,2t+1,2t+8,2t+9) is one contiguous LDS.64.
// Dot products are invariant since both GEMM operands share the permutation.

// ---------------- global scratch (allocation-free rule) ----------------
__device__ __half g_Q [(size_t)BATCH*SEQ*HID];   // scaled, fp16, k-perm
__device__ __half g_K [(size_t)BATCH*SEQ*HID];   // fp16, k-perm
__device__ __half g_Vt[(size_t)BATCH*HID*SEQ];   // V^T [b][h][s], fp16, s-perm
__device__ __half g_P [(size_t)BATCH*SEQ*SEQ];   // probs fp16, s-perm (256 MB)
__device__ float  g_rowsum[BATCH*SEQ];

// ======================= helpers =======================
__device__ __forceinline__ uint32_t smem_u32(const void* p) {
    uint32_t a;
    asm("{ .reg .u64 t; cvta.to.shared.u64 t, %1; cvt.u32.u64 %0, t; }" : "=r"(a) : "l"(p));
    return a;
}
__device__ __forceinline__ void cp16(uint32_t saddr, const void* g) {
    asm volatile("cp.async.cg.shared.global [%0], [%1], 16;"
                 :: "r"(saddr), "l"(__cvta_generic_to_global(g)) : "memory");
}
__device__ __forceinline__ void mma_f16(float* d, const uint32_t* a, const uint32_t* b) {
    asm volatile(
        "mma.sync.aligned.m16n8k16.row.col.f32.f16.f16.f32 "
        "{%0,%1,%2,%3}, {%4,%5,%6,%7}, {%8,%9}, {%0,%1,%2,%3};"
        : "+f"(d[0]), "+f"(d[1]), "+f"(d[2]), "+f"(d[3])
        : "r"(a[0]), "r"(a[1]), "r"(a[2]), "r"(a[3]), "r"(b[0]), "r"(b[1]));
}

// ---------------- fused QKV projection (writes permuted fp16 layouts) ----------------
__global__ __launch_bounds__(256) void qkv_proj_kernel(
    const float* __restrict__ x,
    const float* __restrict__ Wq, const float* __restrict__ bq,
    const float* __restrict__ Wk, const float* __restrict__ bk,
    const float* __restrict__ Wv, const float* __restrict__ bv)
{
    extern __shared__ float psm[];
    float* sX = psm;            // [128][64]
    float* sW = psm + 128*64;   // [64][128]

    const float* Wsel; const float* bsel;
    if (blockIdx.z == 0)      { Wsel = Wq; bsel = bq; }
    else if (blockIdx.z == 1) { Wsel = Wk; bsel = bk; }
    else                      { Wsel = Wv; bsel = bv; }

    const int row0 = blockIdx.x * 128;
    const int col0 = blockIdx.y * 128;
    const int tid  = threadIdx.x;

    #pragma unroll
    for (int i = 0; i < 8; i++) {
        int idx = i*256 + tid;
        int r = idx >> 4, c4 = idx & 15;
        *(float4*)&sX[r*64 + c4*4] = *(const float4*)&x[(size_t)(row0+r)*DIN + c4*4];
    }
    #pragma unroll
    for (int i = 0; i < 8; i++) {
        int idx = i*256 + tid;
        int r = idx >> 5, c4 = idx & 31;
        *(float4*)&sW[r*128 + c4*4] = *(const float4*)&Wsel[(size_t)r*HID + col0 + c4*4];
    }
    __syncthreads();

    const int ty = tid >> 4, tx = tid & 15;
    float acc[8][8];
    #pragma unroll
    for (int i = 0; i < 8; i++)
        #pragma unroll
        for (int j = 0; j < 8; j++) acc[i][j] = 0.0f;

    #pragma unroll 8
    for (int k = 0; k < 64; k++) {
        float xr[8];
        #pragma unroll
        for (int i = 0; i < 8; i++) xr[i] = sX[(ty*8+i)*64 + k];
        float4 w0 = *(const float4*)&sW[k*128 + tx*8];
        float4 w1 = *(const float4*)&sW[k*128 + tx*8 + 4];
        #pragma unroll
        for (int i = 0; i < 8; i++) {
            acc[i][0] += xr[i]*w0.x; acc[i][1] += xr[i]*w0.y;
            acc[i][2] += xr[i]*w0.z; acc[i][3] += xr[i]*w0.w;
            acc[i][4] += xr[i]*w1.x; acc[i][5] += xr[i]*w1.y;
            acc[i][6] += xr[i]*w1.z; acc[i][7] += xr[i]*w1.w;
        }
    }

    float bb[8];
    #pragma unroll
    for (int j = 0; j < 8; j++) bb[j] = __ldg(&bsel[col0 + tx*8 + j]);

    if (blockIdx.z == 2) {
        // V^T: fixed col h -> 8 consecutive s values (half of a 16-group).
        int row_base = row0 + ty*8;
        int bb_i = row_base >> 12;
        int s0 = row_base & (SEQ-1);
        int h8 = (s0 >> 3) & 1;          // low or high half of the 16-group
        int grp = s0 & ~15;
        #pragma unroll
        for (int j = 0; j < 8; j++) {
            int col = col0 + tx*8 + j;
            __half* dst = &g_Vt[((size_t)bb_i*HID + col)*SEQ + grp];
            __half v[8];
            #pragma unroll
            for (int i = 0; i < 8; i++) v[i] = __float2half_rn(acc[i][j] + bb[j]);
            #pragma unroll
            for (int t = 0; t < 4; t++) {
                __half2 h2; h2.x = v[2*t]; h2.y = v[2*t+1];
                *(__half2*)(dst + 4*t + 2*h8) = h2;
            }
        }
    } else {
        __half* osel = (blockIdx.z == 0) ? g_Q : g_K;
        float scale = (blockIdx.z == 0) ? RSCALE : 1.0f;
        int colb = col0 + tx*8;
        int h8 = (colb >> 3) & 1;
        int grp = colb & ~15;
        #pragma unroll
        for (int i = 0; i < 8; i++) {
            __half a[8];
            #pragma unroll
            for (int j = 0; j < 8; j++) a[j] = __float2half_rn((acc[i][j] + bb[j])*scale);
            __half* dst = osel + (size_t)(row0 + ty*8 + i)*HID + grp;
            #pragma unroll
            for (int t = 0; t < 4; t++) {
                __half2 h2; h2.x = a[2*t]; h2.y = a[2*t+1];
                *(__half2*)(dst + 4*t + 2*h8) = h2;
            }
        }
    }
}

// ---------------- rowsum zero ----------------
__global__ void zero_rowsum_kernel() {
    int i = blockIdx.x*256 + threadIdx.x;
    if (i < BATCH*SEQ) g_rowsum[i] = 0.0f;
}

// ======================= fp16 mma.sync GEMM (k-permuted operands) =======================
// C[128,128] per CTA; 8 warps as 2(M) x 4(N); warp tile 64x32.
// K chunked by 64 halves (128 B/row), 2-stage cp.async pipeline,
// smem row pitch 160 B (conflict-free LDS.64 fragment loads).
// mode 0: P = fp16(exp(A.B^T)) stored k-perm, atomicAdd row sums
// mode 1: O = (A.B^T)/rowsum, fp32 normal layout
#define KCH 64
#define PITCHB 160
#define TILEB (128*PITCHB)            // 20480 B
#define STAGEB (2*TILEB)              // 40960 B
#define SMEM_GEMM (2*STAGEB)          // 81920 B

__global__ __launch_bounds__(256, 2) void gemm_f16_kernel(
    const __half* __restrict__ Abase, const __half* __restrict__ Bbase,
    void* __restrict__ Cbase,
    int Kdim, size_t aBatch, size_t bBatch, size_t cBatch, int cld, int mode)
{
    extern __shared__ char sm[];
    const int tid  = threadIdx.x;
    const int wid  = tid >> 5, lane = tid & 31;
    const int warp_m = wid >> 2, warp_n = wid & 3;
    const int g = lane >> 2, tig = lane & 3;
    const int b = blockIdx.z, mt = blockIdx.y, nt = blockIdx.x;

    const __half* A = Abase + (size_t)b*aBatch + (size_t)mt*128*Kdim;
    const __half* B = Bbase + (size_t)b*bBatch + (size_t)nt*128*Kdim;

    const uint32_t smem_base = smem_u32(sm);
    const int ldrow = tid >> 3, ldf4 = tid & 7;          // 8 threads x 16B = 128B row
    const size_t aRow = (size_t)ldrow*Kdim + ldf4*8;     // element offset (halves)
    const size_t rowStep = (size_t)32*Kdim;
    const uint32_t sRow = ldrow*PITCHB + ldf4*16;

    float acc[4][4][4];
    #pragma unroll
    for (int i = 0; i < 4; i++)
        #pragma unroll
        for (int j = 0; j < 4; j++)
            #pragma unroll
            for (int v = 0; v < 4; v++) acc[i][j][v] = 0.0f;

    const int NCH = Kdim / KCH;

    // fragment smem base pointers (per stage)
    const char* pA0 = sm + (warp_m*64 + g)*PITCHB + 8*tig;
    const char* pB0 = sm + TILEB + (warp_n*32 + g)*PITCHB + 8*tig;

    // ---- prologue: chunk 0 -> stage 0 ----
    {
        const __half* Ak = A;
        const __half* Bk = B;
        #pragma unroll
        for (int i = 0; i < 4; i++) {
            cp16(smem_base + i*32*PITCHB + sRow,         Ak + aRow + i*rowStep);
            cp16(smem_base + TILEB + i*32*PITCHB + sRow, Bk + aRow + i*rowStep);
        }
        asm volatile("cp.async.commit_group;" ::: "memory");
    }

    for (int c = 0; c < NCH; ++c) {
        if (c + 1 < NCH) {
            const uint32_t stoff = ((c+1) & 1) ? (uint32_t)STAGEB : 0u;
            const __half* Ak = A + (size_t)(c+1)*KCH;
            const __half* Bk = B + (size_t)(c+1)*KCH;
            #pragma unroll
            for (int i = 0; i < 4; i++) {
                cp16(smem_base + stoff + i*32*PITCHB + sRow,         Ak + aRow + i*rowStep);
                cp16(smem_base + stoff + TILEB + i*32*PITCHB + sRow, Bk + aRow + i*rowStep);
            }
            asm volatile("cp.async.commit_group;" ::: "memory");
            asm volatile("cp.async.wait_group 1;" ::: "memory");
        } else {
            asm volatile("cp.async.wait_group 0;" ::: "memory");
        }
        __syncthreads();

        const char* pA = pA0 + ((c & 1) ? STAGEB : 0);
        const char* pB = pB0 + ((c & 1) ? STAGEB : 0);

        #pragma unroll
        for (int kk = 0; kk < 4; kk++) {          // 4 x K=16 = chunk 64
            const int koff = kk*32;               // 16 halves = 32 B
            uint32_t af[4][4];
            #pragma unroll
            for (int am = 0; am < 4; am++) {
                float2 lo = *(const float2*)(pA + am*2560 + koff);          // row g
                float2 hi = *(const float2*)(pA + am*2560 + 1280 + koff);   // row g+8
                af[am][0] = __float_as_uint(lo.x);
                af[am][1] = __float_as_uint(hi.x);
                af[am][2] = __float_as_uint(lo.y);
                af[am][3] = __float_as_uint(hi.y);
            }
            uint32_t bf[4][2];
            #pragma unroll
            for (int bn = 0; bn < 4; bn++) {
                float2 bv = *(const float2*)(pB + bn*1280 + koff);
                bf[bn][0] = __float_as_uint(bv.x);
                bf[bn][1] = __float_as_uint(bv.y);
            }
            #pragma unroll
            for (int am = 0; am < 4; am++)
                #pragma unroll
                for (int bn = 0; bn < 4; bn++)
                    mma_f16(acc[am][bn], af[am], bf[bn]);
        }
        __syncthreads();
    }

    // ================= epilogue =================
    #pragma unroll
    for (int am = 0; am < 4; am++) {
        const int r0 = mt*128 + warp_m*64 + am*16 + g;
        const int r1 = r0 + 8;
        if (mode == 0) {
            __half* C = (__half*)Cbase;
            float s0 = 0.0f, s1 = 0.0f;
            #pragma unroll
            for (int bn = 0; bn < 4; bn++) {
                // permuted position of this thread's col pair within its 16-group
                const int colp = nt*128 + warp_n*32 + (bn >> 1)*16 + 4*tig + 2*(bn & 1);
                __half h0 = __float2half_rn(__expf(acc[am][bn][0]));
                __half h1 = __float2half_rn(__expf(acc[am][bn][1]));
                __half h2v = __float2half_rn(__expf(acc[am][bn][2]));
                __half h3 = __float2half_rn(__expf(acc[am][bn][3]));
                s0 += __half2float(h0) + __half2float(h1);
                s1 += __half2float(h2v) + __half2float(h3);
                __half2 o0; o0.x = h0;  o0.y = h1;
                __half2 o1; o1.x = h2v; o1.y = h3;
                *(__half2*)(C + (size_t)b*cBatch + (size_t)r0*cld + colp) = o0;
                *(__half2*)(C + (size_t)b*cBatch + (size_t)r1*cld + colp) = o1;
            }
            s0 += __shfl_xor_sync(0xffffffffu, s0, 1);
            s0 += __shfl_xor_sync(0xffffffffu, s0, 2);
            s1 += __shfl_xor_sync(0xffffffffu, s1, 1);
            s1 += __shfl_xor_sync(0xffffffffu, s1, 2);
            if (tig == 0) {
                atomicAdd(&g_rowsum[b*SEQ + r0], s0);
                atomicAdd(&g_rowsum[b*SEQ + r1], s1);
            }
        } else {
            float* C = (float*)Cbase;
            float inv0 = 1.0f / g_rowsum[b*SEQ + r0];
            float inv1 = 1.0f / g_rowsum[b*SEQ + r1];
            #pragma unroll
            for (int bn = 0; bn < 4; bn++) {
                const int col = nt*128 + warp_n*32 + bn*8 + 2*tig;
                float2 o0; o0.x = acc[am][bn][0]*inv0; o0.y = acc[am][bn][1]*inv0;
                float2 o1; o1.x = acc[am][bn][2]*inv1; o1.y = acc[am][bn][3]*inv1;
                *(float2*)(C + (size_t)b*cBatch + (size_t)r0*cld + col) = o0;
                *(float2*)(C + (size_t)b*cBatch + (size_t)r1*cld + col) = o1;
            }
        }
    }
}

// ---------------- launcher ----------------
extern "C" void kernel_launch(void* const* d_in, const int* in_sizes, int n_in,
                              void* d_out, int out_size)
{
    const float* x  = (const float*)d_in[0];
    const float* Wq = (const float*)d_in[1];
    const float* bq = (const float*)d_in[2];
    const float* Wk = (const float*)d_in[3];
    const float* bk = (const float*)d_in[4];
    const float* Wv = (const float*)d_in[5];
    const float* bv = (const float*)d_in[6];
    float* out = (float*)d_out;

    cudaFuncSetAttribute(qkv_proj_kernel, cudaFuncAttributeMaxDynamicSharedMemorySize, 64*1024);
    cudaFuncSetAttribute(gemm_f16_kernel, cudaFuncAttributeMaxDynamicSharedMemorySize, SMEM_GEMM);

    __half *g_Q_p, *g_K_p, *g_Vt_p, *g_P_p;
    cudaGetSymbolAddress((void**)&g_Q_p,  g_Q);
    cudaGetSymbolAddress((void**)&g_K_p,  g_K);
    cudaGetSymbolAddress((void**)&g_Vt_p, g_Vt);
    cudaGetSymbolAddress((void**)&g_P_p,  g_P);

    // 1) QKV projections (permuted fp16 layouts)
    dim3 pg(M_ROWS/128, HID/128, 3);
    qkv_proj_kernel<<<pg, 256, 64*1024>>>(x, Wq, bq, Wk, bk, Wv, bv);

    // 2) zero row sums
    zero_rowsum_kernel<<<(BATCH*SEQ + 255)/256, 256>>>();

    // 3) P = exp(Q.K^T), rowsum accumulated
    dim3 sg(SEQ/128, SEQ/128, BATCH);   // (32, 32, 8)
    gemm_f16_kernel<<<sg, 256, SMEM_GEMM>>>(
        g_Q_p, g_K_p, (void*)g_P_p,
        HID, (size_t)SEQ*HID, (size_t)SEQ*HID, (size_t)SEQ*SEQ, SEQ, 0);

    // 4) O = (P.Vt^T) / rowsum
    dim3 og(HID/128, SEQ/128, BATCH);   // (4, 32, 8)
    gemm_f16_kernel<<<og, 256, SMEM_GEMM>>>(
        g_P_p, g_Vt_p, (void*)out,
        SEQ, (size_t)SEQ*SEQ, (size_t)HID*SEQ, (size_t)SEQ*HID, HID, 1);
}

// round 11
// speedup vs baseline: 18.5467x; 1.1281x over previous
#include <cuda_runtime.h>
#include <cuda_fp16.h>
#include <cstdint>
#include <math.h>

#define BATCH 8
#define SEQ   4096
#define DIN   64
#define HID   512
#define M_ROWS (BATCH*SEQ)
#define RSCALE 0.044194173824159216f  /* 1/sqrt(512) */

// Plain row-major fp16 layouts (k contiguous). ldmatrix does fragment shuffling.
// ---------------- global scratch (allocation-free rule) ----------------
__device__ __half g_Q [(size_t)BATCH*SEQ*HID];   // scaled by RSCALE
__device__ __half g_K [(size_t)BATCH*SEQ*HID];
__device__ __half g_Vt[(size_t)BATCH*HID*SEQ];   // V^T [b][h][s]
__device__ __half g_P [(size_t)BATCH*SEQ*SEQ];   // probs fp16 (256 MB)
__device__ float  g_rowsum[BATCH*SEQ];

// ======================= helpers =======================
__device__ __forceinline__ uint32_t smem_u32(const void* p) {
    uint32_t a;
    asm("{ .reg .u64 t; cvta.to.shared.u64 t, %1; cvt.u32.u64 %0, t; }" : "=r"(a) : "l"(p));
    return a;
}
__device__ __forceinline__ void cp16(uint32_t saddr, const void* g) {
    asm volatile("cp.async.cg.shared.global [%0], [%1], 16;"
                 :: "r"(saddr), "l"(__cvta_generic_to_global(g)) : "memory");
}
__device__ __forceinline__ void mma_f16(float* d, const uint32_t* a, const uint32_t* b) {
    asm volatile(
        "mma.sync.aligned.m16n8k16.row.col.f32.f16.f16.f32 "
        "{%0,%1,%2,%3}, {%4,%5,%6,%7}, {%8,%9}, {%0,%1,%2,%3};"
        : "+f"(d[0]), "+f"(d[1]), "+f"(d[2]), "+f"(d[3])
        : "r"(a[0]), "r"(a[1]), "r"(a[2]), "r"(a[3]), "r"(b[0]), "r"(b[1]));
}
__device__ __forceinline__ void ldsm_x4(uint32_t& r0, uint32_t& r1, uint32_t& r2, uint32_t& r3,
                                        uint32_t addr) {
    asm volatile("ldmatrix.sync.aligned.m8n8.x4.shared.b16 {%0,%1,%2,%3}, [%4];"
                 : "=r"(r0), "=r"(r1), "=r"(r2), "=r"(r3) : "r"(addr));
}
__device__ __forceinline__ uint32_t pack2(float a, float b) {
    __half2 h = __floats2half2_rn(a, b);
    return *(uint32_t*)&h;
}

// ---------------- fused QKV projection (plain fp16 outputs) ----------------
__global__ __launch_bounds__(256) void qkv_proj_kernel(
    const float* __restrict__ x,
    const float* __restrict__ Wq, const float* __restrict__ bq,
    const float* __restrict__ Wk, const float* __restrict__ bk,
    const float* __restrict__ Wv, const float* __restrict__ bv)
{
    extern __shared__ float psm[];
    float* sX = psm;            // [128][64]
    float* sW = psm + 128*64;   // [64][128]

    const float* Wsel; const float* bsel;
    if (blockIdx.z == 0)      { Wsel = Wq; bsel = bq; }
    else if (blockIdx.z == 1) { Wsel = Wk; bsel = bk; }
    else                      { Wsel = Wv; bsel = bv; }

    const int row0 = blockIdx.x * 128;
    const int col0 = blockIdx.y * 128;
    const int tid  = threadIdx.x;

    #pragma unroll
    for (int i = 0; i < 8; i++) {
        int idx = i*256 + tid;
        int r = idx >> 4, c4 = idx & 15;
        *(float4*)&sX[r*64 + c4*4] = *(const float4*)&x[(size_t)(row0+r)*DIN + c4*4];
    }
    #pragma unroll
    for (int i = 0; i < 8; i++) {
        int idx = i*256 + tid;
        int r = idx >> 5, c4 = idx & 31;
        *(float4*)&sW[r*128 + c4*4] = *(const float4*)&Wsel[(size_t)r*HID + col0 + c4*4];
    }
    __syncthreads();

    const int ty = tid >> 4, tx = tid & 15;
    float acc[8][8];
    #pragma unroll
    for (int i = 0; i < 8; i++)
        #pragma unroll
        for (int j = 0; j < 8; j++) acc[i][j] = 0.0f;

    #pragma unroll 8
    for (int k = 0; k < 64; k++) {
        float xr[8];
        #pragma unroll
        for (int i = 0; i < 8; i++) xr[i] = sX[(ty*8+i)*64 + k];
        float4 w0 = *(const float4*)&sW[k*128 + tx*8];
        float4 w1 = *(const float4*)&sW[k*128 + tx*8 + 4];
        #pragma unroll
        for (int i = 0; i < 8; i++) {
            acc[i][0] += xr[i]*w0.x; acc[i][1] += xr[i]*w0.y;
            acc[i][2] += xr[i]*w0.z; acc[i][3] += xr[i]*w0.w;
            acc[i][4] += xr[i]*w1.x; acc[i][5] += xr[i]*w1.y;
            acc[i][6] += xr[i]*w1.z; acc[i][7] += xr[i]*w1.w;
        }
    }

    float bb[8];
    #pragma unroll
    for (int j = 0; j < 8; j++) bb[j] = __ldg(&bsel[col0 + tx*8 + j]);

    if (blockIdx.z == 2) {
        // V^T: fixed col h -> 8 consecutive s values; one 16B store.
        int row_base = row0 + ty*8;
        int bb_i = row_base >> 12;
        int s0 = row_base & (SEQ-1);
        #pragma unroll
        for (int j = 0; j < 8; j++) {
            int col = col0 + tx*8 + j;
            __half* dst = &g_Vt[((size_t)bb_i*HID + col)*SEQ + s0];
            uint4 w;
            w.x = pack2(acc[0][j]+bb[j], acc[1][j]+bb[j]);
            w.y = pack2(acc[2][j]+bb[j], acc[3][j]+bb[j]);
            w.z = pack2(acc[4][j]+bb[j], acc[5][j]+bb[j]);
            w.w = pack2(acc[6][j]+bb[j], acc[7][j]+bb[j]);
            *(uint4*)dst = w;
        }
    } else {
        __half* osel = (blockIdx.z == 0) ? g_Q : g_K;
        float scale = (blockIdx.z == 0) ? RSCALE : 1.0f;
        #pragma unroll
        for (int i = 0; i < 8; i++) {
            __half* dst = osel + (size_t)(row0 + ty*8 + i)*HID + col0 + tx*8;
            uint4 w;
            w.x = pack2((acc[i][0]+bb[0])*scale, (acc[i][1]+bb[1])*scale);
            w.y = pack2((acc[i][2]+bb[2])*scale, (acc[i][3]+bb[3])*scale);
            w.z = pack2((acc[i][4]+bb[4])*scale, (acc[i][5]+bb[5])*scale);
            w.w = pack2((acc[i][6]+bb[6])*scale, (acc[i][7]+bb[7])*scale);
            *(uint4*)dst = w;
        }
    }
}

// ---------------- rowsum zero ----------------
__global__ void zero_rowsum_kernel() {
    int i = blockIdx.x*256 + threadIdx.x;
    if (i < BATCH*SEQ) g_rowsum[i] = 0.0f;
}

// ======================= fp16 mma.sync GEMM (ldmatrix + swizzle) =======================
// C[128,128] per CTA; 8 warps as 2(M) x 4(N); warp tile 64x32.
// K chunked by 64 halves (128 B/row). 3-stage cp.async pipeline.
// smem tile rows 128 B with XOR swizzle: 16B chunk f of row r stored at (f ^ (r&7))*16.
// mode 0: P = fp16(exp(A.B^T)), atomicAdd row sums
// mode 1: O = (A.B^T)/rowsum, fp32
#define KCH 64
#define TILEB (128*128)               // 16384 B
#define STAGEB (2*TILEB)              // 32768 B (A + B)
#define NSTAGE 3
#define SMEM_GEMM (NSTAGE*STAGEB)     // 98304 B

__global__ __launch_bounds__(256, 2) void gemm_f16_kernel(
    const __half* __restrict__ Abase, const __half* __restrict__ Bbase,
    void* __restrict__ Cbase,
    int Kdim, size_t aBatch, size_t bBatch, size_t cBatch, int cld, int mode)
{
    extern __shared__ char sm[];
    const int tid  = threadIdx.x;
    const int wid  = tid >> 5, lane = tid & 31;
    const int warp_m = wid >> 2, warp_n = wid & 3;
    const int g = lane >> 2, tig = lane & 3;
    const int b = blockIdx.z, mt = blockIdx.y, nt = blockIdx.x;

    const __half* A = Abase + (size_t)b*aBatch + (size_t)mt*128*Kdim;
    const __half* B = Bbase + (size_t)b*bBatch + (size_t)nt*128*Kdim;

    const uint32_t smem_base = smem_u32(sm);

    // cp.async geometry: thread -> (row = tid>>3 (+i*32), 16B chunk = tid&7)
    const int ldrow = tid >> 3, ldf4 = tid & 7;
    const uint32_t sRow = (uint32_t)ldrow*128 + (uint32_t)((ldf4 ^ (ldrow & 7)) * 16);
    const size_t aRowOff = (size_t)ldrow*Kdim + ldf4*8;
    const size_t rowStep = (size_t)32*Kdim;

    // ldmatrix lane geometry
    const int lrow8 = lane & 7;
    const int rowA = lrow8 + 8*((lane >> 3) & 1);   // A x4: q0 rows0-7 klo, q1 rows8-15 klo, q2 rows0-7 khi, q3 rows8-15 khi
    const int kcA  = lane >> 4;
    const int rowB = lrow8 + 8*(lane >> 4);         // B x4: q0 n0-7 klo, q1 n0-7 khi, q2 n8-15 klo, q3 n8-15 khi
    const int kcB  = (lane >> 3) & 1;
    const uint32_t aBase0 = smem_base + (uint32_t)(warp_m*64 + rowA)*128;
    const uint32_t bBase0 = smem_base + TILEB + (uint32_t)(warp_n*32 + rowB)*128;
    uint32_t xA[4], xB[4];
    #pragma unroll
    for (int kk = 0; kk < 4; kk++) {
        xA[kk] = (uint32_t)(((2*kk + kcA) ^ lrow8) * 16);
        xB[kk] = (uint32_t)(((2*kk + kcB) ^ lrow8) * 16);
    }

    float acc[4][4][4];
    #pragma unroll
    for (int i = 0; i < 4; i++)
        #pragma unroll
        for (int j = 0; j < 4; j++)
            #pragma unroll
            for (int v = 0; v < 4; v++) acc[i][j][v] = 0.0f;

    const int NCH = Kdim / KCH;

    // ---- prologue: chunks 0,1 -> stages 0,1 (one commit each) ----
    #pragma unroll
    for (int p = 0; p < 2; p++) {
        const __half* Ak = A + p*KCH;
        const __half* Bk = B + p*KCH;
        uint32_t st = smem_base + (uint32_t)p*STAGEB;
        #pragma unroll
        for (int i = 0; i < 4; i++) {
            cp16(st + sRow + i*4096,         Ak + aRowOff + i*rowStep);
            cp16(st + TILEB + sRow + i*4096, Bk + aRowOff + i*rowStep);
        }
        asm volatile("cp.async.commit_group;" ::: "memory");
    }

    const __half* gA = A + 2*KCH;
    const __half* gB = B + 2*KCH;
    int stR = 0, stW = 2;

    for (int c = 0; c < NCH; ++c) {
        if (c + 2 < NCH) {
            uint32_t st = smem_base + (uint32_t)stW*STAGEB;
            #pragma unroll
            for (int i = 0; i < 4; i++) {
                cp16(st + sRow + i*4096,         gA + aRowOff + i*rowStep);
                cp16(st + TILEB + sRow + i*4096, gB + aRowOff + i*rowStep);
            }
            gA += KCH; gB += KCH;
        }
        asm volatile("cp.async.commit_group;" ::: "memory");   // one group per iter (possibly empty)
        asm volatile("cp.async.wait_group 2;" ::: "memory");   // chunk c complete
        __syncthreads();

        const uint32_t aB = aBase0 + (uint32_t)stR*STAGEB;
        const uint32_t bB = bBase0 + (uint32_t)stR*STAGEB;

        #pragma unroll
        for (int kk = 0; kk < 4; kk++) {          // 4 x K=16 = chunk 64
            uint32_t af[4][4];
            #pragma unroll
            for (int am = 0; am < 4; am++)
                ldsm_x4(af[am][0], af[am][1], af[am][2], af[am][3],
                        aB + am*2048 + xA[kk]);
            uint32_t bf[2][4];
            ldsm_x4(bf[0][0], bf[0][1], bf[0][2], bf[0][3], bB + xB[kk]);
            ldsm_x4(bf[1][0], bf[1][1], bf[1][2], bf[1][3], bB + 2048 + xB[kk]);
            #pragma unroll
            for (int am = 0; am < 4; am++)
                #pragma unroll
                for (int bn = 0; bn < 4; bn++)
                    mma_f16(acc[am][bn], af[am], &bf[bn >> 1][2*(bn & 1)]);
        }
        __syncthreads();
        stR = (stR == 2) ? 0 : stR + 1;
        stW = (stW == 2) ? 0 : stW + 1;
    }

    // ================= epilogue =================
    #pragma unroll
    for (int am = 0; am < 4; am++) {
        const int r0 = mt*128 + warp_m*64 + am*16 + g;
        const int r1 = r0 + 8;
        if (mode == 0) {
            __half* C = (__half*)Cbase;
            float s0 = 0.0f, s1 = 0.0f;
            #pragma unroll
            for (int bn = 0; bn < 4; bn++) {
                const int col = nt*128 + warp_n*32 + bn*8 + 2*tig;
                __half h0 = __float2half_rn(__expf(acc[am][bn][0]));
                __half h1 = __float2half_rn(__expf(acc[am][bn][1]));
                __half h2v = __float2half_rn(__expf(acc[am][bn][2]));
                __half h3 = __float2half_rn(__expf(acc[am][bn][3]));
                s0 += __half2float(h0) + __half2float(h1);
                s1 += __half2float(h2v) + __half2float(h3);
                __half2 o0; o0.x = h0;  o0.y = h1;
                __half2 o1; o1.x = h2v; o1.y = h3;
                *(__half2*)(C + (size_t)b*cBatch + (size_t)r0*cld + col) = o0;
                *(__half2*)(C + (size_t)b*cBatch + (size_t)r1*cld + col) = o1;
            }
            s0 += __shfl_xor_sync(0xffffffffu, s0, 1);
            s0 += __shfl_xor_sync(0xffffffffu, s0, 2);
            s1 += __shfl_xor_sync(0xffffffffu, s1, 1);
            s1 += __shfl_xor_sync(0xffffffffu, s1, 2);
            if (tig == 0) {
                atomicAdd(&g_rowsum[b*SEQ + r0], s0);
                atomicAdd(&g_rowsum[b*SEQ + r1], s1);
            }
        } else {
            float* C = (float*)Cbase;
            float inv0 = 1.0f / g_rowsum[b*SEQ + r0];
            float inv1 = 1.0f / g_rowsum[b*SEQ + r1];
            #pragma unroll
            for (int bn = 0; bn < 4; bn++) {
                const int col = nt*128 + warp_n*32 + bn*8 + 2*tig;
                float2 o0; o0.x = acc[am][bn][0]*inv0; o0.y = acc[am][bn][1]*inv0;
                float2 o1; o1.x = acc[am][bn][2]*inv1; o1.y = acc[am][bn][3]*inv1;
                *(float2*)(C + (size_t)b*cBatch + (size_t)r0*cld + col) = o0;
                *(float2*)(C + (size_t)b*cBatch + (size_t)r1*cld + col) = o1;
            }
        }
    }
}

// ---------------- launcher ----------------
extern "C" void kernel_launch(void* const* d_in, const int* in_sizes, int n_in,
                              void* d_out, int out_size)
{
    const float* x  = (const float*)d_in[0];
    const float* Wq = (const float*)d_in[1];
    const float* bq = (const float*)d_in[2];
    const float* Wk = (const float*)d_in[3];
    const float* bk = (const float*)d_in[4];
    const float* Wv = (const float*)d_in[5];
    const float* bv = (const float*)d_in[6];
    float* out = (float*)d_out;

    cudaFuncSetAttribute(qkv_proj_kernel, cudaFuncAttributeMaxDynamicSharedMemorySize, 64*1024);
    cudaFuncSetAttribute(gemm_f16_kernel, cudaFuncAttributeMaxDynamicSharedMemorySize, SMEM_GEMM);

    __half *g_Q_p, *g_K_p, *g_Vt_p, *g_P_p;
    cudaGetSymbolAddress((void**)&g_Q_p,  g_Q);
    cudaGetSymbolAddress((void**)&g_K_p,  g_K);
    cudaGetSymbolAddress((void**)&g_Vt_p, g_Vt);
    cudaGetSymbolAddress((void**)&g_P_p,  g_P);

    // 1) QKV projections (plain fp16 outputs)
    dim3 pg(M_ROWS/128, HID/128, 3);
    qkv_proj_kernel<<<pg, 256, 64*1024>>>(x, Wq, bq, Wk, bk, Wv, bv);

    // 2) zero row sums
    zero_rowsum_kernel<<<(BATCH*SEQ + 255)/256, 256>>>();

    // 3) P = exp(Q.K^T), rowsum accumulated
    dim3 sg(SEQ/128, SEQ/128, BATCH);   // (32, 32, 8)
    gemm_f16_kernel<<<sg, 256, SMEM_GEMM>>>(
        g_Q_p, g_K_p, (void*)g_P_p,
        HID, (size_t)SEQ*HID, (size_t)SEQ*HID, (size_t)SEQ*SEQ, SEQ, 0);

    // 4) O = (P.Vt^T) / rowsum
    dim3 og(HID/128, SEQ/128, BATCH);   // (4, 32, 8)
    gemm_f16_kernel<<<og, 256, SMEM_GEMM>>>(
        g_P_p, g_Vt_p, (void*)out,
        SEQ, (size_t)SEQ*SEQ, (size_t)HID*SEQ, (size_t)SEQ*HID, HID, 1);
}

// round 12
// speedup vs baseline: 21.3590x; 1.1516x over previous
#include <cuda_runtime.h>
#include <cuda_fp16.h>
#include <cstdint>
#include <math.h>

#define BATCH 8
#define SEQ   4096
#define DIN   64
#define HID   512
#define M_ROWS (BATCH*SEQ)
#define RSCALE 0.044194173824159216f  /* 1/sqrt(512) */

// ---------------- global scratch (allocation-free rule) ----------------
__device__ __half g_Xh[(size_t)M_ROWS*DIN];      // x in fp16
__device__ __half g_Wt[3*(size_t)HID*DIN];       // W^T fp16: [w][h][d]
__device__ __half g_Q [(size_t)BATCH*SEQ*HID];   // scaled by RSCALE
__device__ __half g_K [(size_t)BATCH*SEQ*HID];
__device__ __half g_Vt[(size_t)BATCH*HID*SEQ];   // V^T [b][h][s]
__device__ __half g_P [(size_t)BATCH*SEQ*SEQ];   // probs fp16 (256 MB)
__device__ float  g_rowsum[BATCH*SEQ];

// ======================= helpers =======================
__device__ __forceinline__ uint32_t smem_u32(const void* p) {
    uint32_t a;
    asm("{ .reg .u64 t; cvta.to.shared.u64 t, %1; cvt.u32.u64 %0, t; }" : "=r"(a) : "l"(p));
    return a;
}
__device__ __forceinline__ void cp16(uint32_t saddr, const void* g) {
    asm volatile("cp.async.cg.shared.global [%0], [%1], 16;"
                 :: "r"(saddr), "l"(__cvta_generic_to_global(g)) : "memory");
}
__device__ __forceinline__ void mma_f16(float* d, const uint32_t* a, const uint32_t* b) {
    asm volatile(
        "mma.sync.aligned.m16n8k16.row.col.f32.f16.f16.f32 "
        "{%0,%1,%2,%3}, {%4,%5,%6,%7}, {%8,%9}, {%0,%1,%2,%3};"
        : "+f"(d[0]), "+f"(d[1]), "+f"(d[2]), "+f"(d[3])
        : "r"(a[0]), "r"(a[1]), "r"(a[2]), "r"(a[3]), "r"(b[0]), "r"(b[1]));
}
__device__ __forceinline__ void ldsm_x4(uint32_t& r0, uint32_t& r1, uint32_t& r2, uint32_t& r3,
                                        uint32_t addr) {
    asm volatile("ldmatrix.sync.aligned.m8n8.x4.shared.b16 {%0,%1,%2,%3}, [%4];"
                 : "=r"(r0), "=r"(r1), "=r"(r2), "=r"(r3) : "r"(addr));
}
__device__ __forceinline__ uint32_t pack2(float a, float b) {
    __half2 h = __floats2half2_rn(a, b);
    return *(uint32_t*)&h;
}

// ---------------- convert: xh, W^T fp16, zero rowsum ----------------
// blocks [0,1024): xh (8 halves/thread); [1024,1072): Wt; [1072,1088): rowsum
__global__ __launch_bounds__(256) void convert_kernel(
    const float* __restrict__ x,
    const float* __restrict__ Wq, const float* __restrict__ Wk, const float* __restrict__ Wv)
{
    const int bid = blockIdx.x, tid = threadIdx.x;
    if (bid < 1024) {
        size_t i8 = ((size_t)bid*256 + tid)*8;
        float4 a = *(const float4*)&x[i8];
        float4 b = *(const float4*)&x[i8+4];
        uint4 o;
        o.x = pack2(a.x, a.y); o.y = pack2(a.z, a.w);
        o.z = pack2(b.x, b.y); o.w = pack2(b.z, b.w);
        *(uint4*)&g_Xh[i8] = o;
    } else if (bid < 1072) {
        // 3*512*64/8 = 12288 threads; Wt[w][h][d0..d0+7] = W[d][h]
        int t = (bid - 1024)*256 + tid;
        int w = t / 4096;                 // 4096 threads per matrix
        int r = t - w*4096;
        int h = r >> 3;
        int d0 = (r & 7)*8;
        const float* W = (w == 0) ? Wq : (w == 1) ? Wk : Wv;
        float f[8];
        #pragma unroll
        for (int j = 0; j < 8; j++) f[j] = W[(size_t)(d0+j)*HID + h];
        uint4 o;
        o.x = pack2(f[0], f[1]); o.y = pack2(f[2], f[3]);
        o.z = pack2(f[4], f[5]); o.w = pack2(f[6], f[7]);
        *(uint4*)&g_Wt[(size_t)w*HID*DIN + (size_t)h*DIN + d0] = o;
    } else {
        int i = ((bid - 1072)*256 + tid)*8;
        #pragma unroll
        for (int j = 0; j < 8; j++) g_rowsum[i+j] = 0.0f;
    }
}

// ---------------- tensor-core QKV projection ----------------
// grid (nt=4, mt=256, z=3); 256 threads; C tile 128(s) x 128(h); K=64 single chunk.
// z=0 -> g_Q (scaled), z=1 -> g_K, z=2 -> g_Vt via smem transpose.
#define PT 136                               // smemT pitch (halves)
#define SMEM_PROJ (32768 + PT*128*2)         // 16KB A + 16KB B + 34KB transpose

__global__ __launch_bounds__(256) void qkv_proj_mma_kernel(
    const float* __restrict__ bq, const float* __restrict__ bk, const float* __restrict__ bv)
{
    extern __shared__ char sm[];
    const uint32_t smem_base = smem_u32(sm);
    const int tid = threadIdx.x;
    const int wid = tid >> 5, lane = tid & 31;
    const int warp_m = wid >> 2, warp_n = wid & 3;
    const int g = lane >> 2, tig = lane & 3;
    const int z = blockIdx.z, mt = blockIdx.y, nt = blockIdx.x;

    const __half* A = g_Xh + (size_t)mt*128*DIN;
    const __half* B = g_Wt + (size_t)z*HID*DIN + (size_t)nt*128*DIN;
    const float* bias = (z == 0) ? bq : (z == 1) ? bk : bv;

    // load both tiles (128 rows x 128B, XOR swizzle)
    const int ldrow = tid >> 3, ldf4 = tid & 7;
    const uint32_t sRow = (uint32_t)ldrow*128 + (uint32_t)((ldf4 ^ (ldrow & 7))*16);
    const size_t gOff = (size_t)ldrow*DIN + ldf4*8;
    #pragma unroll
    for (int i = 0; i < 4; i++) {
        cp16(smem_base + sRow + i*4096,         A + gOff + (size_t)i*32*DIN);
        cp16(smem_base + 16384 + sRow + i*4096, B + gOff + (size_t)i*32*DIN);
    }
    asm volatile("cp.async.commit_group;" ::: "memory");
    asm volatile("cp.async.wait_group 0;" ::: "memory");
    __syncthreads();

    // ldmatrix geometry (identical to main GEMM)
    const int lrow8 = lane & 7;
    const int rowA = lrow8 + 8*((lane >> 3) & 1);
    const int kcA  = lane >> 4;
    const int rowB = lrow8 + 8*(lane >> 4);
    const int kcB  = (lane >> 3) & 1;
    const uint32_t aB = smem_base + (uint32_t)(warp_m*64 + rowA)*128;
    const uint32_t bB = smem_base + 16384 + (uint32_t)(warp_n*32 + rowB)*128;

    float acc[4][4][4];
    #pragma unroll
    for (int i = 0; i < 4; i++)
        #pragma unroll
        for (int j = 0; j < 4; j++)
            #pragma unroll
            for (int v = 0; v < 4; v++) acc[i][j][v] = 0.0f;

    #pragma unroll
    for (int kk = 0; kk < 4; kk++) {
        const uint32_t xA = (uint32_t)(((2*kk + kcA) ^ lrow8)*16);
        const uint32_t xB = (uint32_t)(((2*kk + kcB) ^ lrow8)*16);
        uint32_t af[4][4];
        #pragma unroll
        for (int am = 0; am < 4; am++)
            ldsm_x4(af[am][0], af[am][1], af[am][2], af[am][3], aB + am*2048 + xA);
        uint32_t bf[2][4];
        ldsm_x4(bf[0][0], bf[0][1], bf[0][2], bf[0][3], bB + xB);
        ldsm_x4(bf[1][0], bf[1][1], bf[1][2], bf[1][3], bB + 2048 + xB);
        #pragma unroll
        for (int am = 0; am < 4; am++)
            #pragma unroll
            for (int bn = 0; bn < 4; bn++)
                mma_f16(acc[am][bn], af[am], &bf[bn >> 1][2*(bn & 1)]);
    }

    // bias per bn (cols gcol, gcol+1)
    float b0[4], b1[4];
    #pragma unroll
    for (int bn = 0; bn < 4; bn++) {
        int gcol = nt*128 + warp_n*32 + bn*8 + 2*tig;
        b0[bn] = __ldg(&bias[gcol]);
        b1[bn] = __ldg(&bias[gcol+1]);
    }

    if (z < 2) {
        __half* osel = (z == 0) ? g_Q : g_K;
        const float sc = (z == 0) ? RSCALE : 1.0f;
        #pragma unroll
        for (int am = 0; am < 4; am++) {
            const int r0 = mt*128 + warp_m*64 + am*16 + g;
            const int r1 = r0 + 8;
            #pragma unroll
            for (int bn = 0; bn < 4; bn++) {
                const int gcol = nt*128 + warp_n*32 + bn*8 + 2*tig;
                *(uint32_t*)(osel + (size_t)r0*HID + gcol) =
                    pack2((acc[am][bn][0]+b0[bn])*sc, (acc[am][bn][1]+b1[bn])*sc);
                *(uint32_t*)(osel + (size_t)r1*HID + gcol) =
                    pack2((acc[am][bn][2]+b0[bn])*sc, (acc[am][bn][3]+b1[bn])*sc);
            }
        }
    } else {
        __half* smT = (__half*)(sm + 32768);
        #pragma unroll
        for (int am = 0; am < 4; am++) {
            const int r0 = warp_m*64 + am*16 + g;
            const int r1 = r0 + 8;
            #pragma unroll
            for (int bn = 0; bn < 4; bn++) {
                const int col = warp_n*32 + bn*8 + 2*tig;
                smT[(col  )*PT + r0] = __float2half_rn(acc[am][bn][0]+b0[bn]);
                smT[(col+1)*PT + r0] = __float2half_rn(acc[am][bn][1]+b1[bn]);
                smT[(col  )*PT + r1] = __float2half_rn(acc[am][bn][2]+b0[bn]);
                smT[(col+1)*PT + r1] = __float2half_rn(acc[am][bn][3]+b1[bn]);
            }
        }
        __syncthreads();
        const int bb = mt >> 5;
        const int s0 = (mt*128) & (SEQ-1);
        #pragma unroll
        for (int j = 0; j < 8; j++) {
            int idx = j*256 + tid;        // 2048 chunks of 8 halves
            int h  = idx >> 4;
            int ch = idx & 15;
            uint4 v = *(uint4*)&smT[h*PT + ch*8];
            *(uint4*)&g_Vt[((size_t)bb*HID + nt*128 + h)*SEQ + s0 + ch*8] = v;
        }
    }
}

// ======================= fp16 mma.sync GEMM (ldmatrix + swizzle) =======================
// C[128,128] per CTA; 8 warps as 2(M) x 4(N); warp tile 64x32.
// K chunked by 64 halves. 3-stage cp.async pipeline, ONE sync per chunk.
// mode 0: P = fp16(exp(A.B^T)), atomicAdd row sums
// mode 1: O = (A.B^T)/rowsum, fp32
#define KCH 64
#define TILEB (128*128)               // 16384 B
#define STAGEB (2*TILEB)              // 32768 B (A + B)
#define NSTAGE 3
#define SMEM_GEMM (NSTAGE*STAGEB)     // 98304 B

__global__ __launch_bounds__(256, 2) void gemm_f16_kernel(
    const __half* __restrict__ Abase, const __half* __restrict__ Bbase,
    void* __restrict__ Cbase,
    int Kdim, size_t aBatch, size_t bBatch, size_t cBatch, int cld, int mode)
{
    extern __shared__ char sm[];
    const int tid  = threadIdx.x;
    const int wid  = tid >> 5, lane = tid & 31;
    const int warp_m = wid >> 2, warp_n = wid & 3;
    const int g = lane >> 2, tig = lane & 3;
    const int b = blockIdx.z, mt = blockIdx.y, nt = blockIdx.x;

    const __half* A = Abase + (size_t)b*aBatch + (size_t)mt*128*Kdim;
    const __half* B = Bbase + (size_t)b*bBatch + (size_t)nt*128*Kdim;

    const uint32_t smem_base = smem_u32(sm);

    const int ldrow = tid >> 3, ldf4 = tid & 7;
    const uint32_t sRow = (uint32_t)ldrow*128 + (uint32_t)((ldf4 ^ (ldrow & 7)) * 16);
    const size_t aRowOff = (size_t)ldrow*Kdim + ldf4*8;
    const size_t rowStep = (size_t)32*Kdim;

    const int lrow8 = lane & 7;
    const int rowA = lrow8 + 8*((lane >> 3) & 1);
    const int kcA  = lane >> 4;
    const int rowB = lrow8 + 8*(lane >> 4);
    const int kcB  = (lane >> 3) & 1;
    const uint32_t aBase0 = smem_base + (uint32_t)(warp_m*64 + rowA)*128;
    const uint32_t bBase0 = smem_base + TILEB + (uint32_t)(warp_n*32 + rowB)*128;
    uint32_t xA[4], xB[4];
    #pragma unroll
    for (int kk = 0; kk < 4; kk++) {
        xA[kk] = (uint32_t)(((2*kk + kcA) ^ lrow8) * 16);
        xB[kk] = (uint32_t)(((2*kk + kcB) ^ lrow8) * 16);
    }

    float acc[4][4][4];
    #pragma unroll
    for (int i = 0; i < 4; i++)
        #pragma unroll
        for (int j = 0; j < 4; j++)
            #pragma unroll
            for (int v = 0; v < 4; v++) acc[i][j][v] = 0.0f;

    const int NCH = Kdim / KCH;

    // ---- prologue: chunks 0,1 -> stages 0,1 ----
    #pragma unroll
    for (int p = 0; p < 2; p++) {
        const __half* Ak = A + p*KCH;
        const __half* Bk = B + p*KCH;
        uint32_t st = smem_base + (uint32_t)p*STAGEB;
        #pragma unroll
        for (int i = 0; i < 4; i++) {
            cp16(st + sRow + i*4096,         Ak + aRowOff + i*rowStep);
            cp16(st + TILEB + sRow + i*4096, Bk + aRowOff + i*rowStep);
        }
        asm volatile("cp.async.commit_group;" ::: "memory");
    }

    const __half* gA = A + 2*KCH;
    const __half* gB = B + 2*KCH;
    int stR = 0, stW = 2;

    for (int c = 0; c < NCH; ++c) {
        asm volatile("cp.async.wait_group 1;" ::: "memory");   // chunk c resident
        __syncthreads();                                       // all reads of stage stW done

        if (c + 2 < NCH) {
            uint32_t st = smem_base + (uint32_t)stW*STAGEB;
            #pragma unroll
            for (int i = 0; i < 4; i++) {
                cp16(st + sRow + i*4096,         gA + aRowOff + i*rowStep);
                cp16(st + TILEB + sRow + i*4096, gB + aRowOff + i*rowStep);
            }
            gA += KCH; gB += KCH;
        }
        asm volatile("cp.async.commit_group;" ::: "memory");   // one group per iter

        const uint32_t aB = aBase0 + (uint32_t)stR*STAGEB;
        const uint32_t bB = bBase0 + (uint32_t)stR*STAGEB;

        #pragma unroll
        for (int kk = 0; kk < 4; kk++) {
            uint32_t af[4][4];
            #pragma unroll
            for (int am = 0; am < 4; am++)
                ldsm_x4(af[am][0], af[am][1], af[am][2], af[am][3],
                        aB + am*2048 + xA[kk]);
            uint32_t bf[2][4];
            ldsm_x4(bf[0][0], bf[0][1], bf[0][2], bf[0][3], bB + xB[kk]);
            ldsm_x4(bf[1][0], bf[1][1], bf[1][2], bf[1][3], bB + 2048 + xB[kk]);
            #pragma unroll
            for (int am = 0; am < 4; am++)
                #pragma unroll
                for (int bn = 0; bn < 4; bn++)
                    mma_f16(acc[am][bn], af[am], &bf[bn >> 1][2*(bn & 1)]);
        }
        stR = (stR == 2) ? 0 : stR + 1;
        stW = (stW == 2) ? 0 : stW + 1;
    }

    // ================= epilogue =================
    #pragma unroll
    for (int am = 0; am < 4; am++) {
        const int r0 = mt*128 + warp_m*64 + am*16 + g;
        const int r1 = r0 + 8;
        if (mode == 0) {
            __half* C = (__half*)Cbase;
            float s0 = 0.0f, s1 = 0.0f;
            #pragma unroll
            for (int bn = 0; bn < 4; bn++) {
                const int col = nt*128 + warp_n*32 + bn*8 + 2*tig;
                __half h0 = __float2half_rn(__expf(acc[am][bn][0]));
                __half h1 = __float2half_rn(__expf(acc[am][bn][1]));
                __half h2v = __float2half_rn(__expf(acc[am][bn][2]));
                __half h3 = __float2half_rn(__expf(acc[am][bn][3]));
                s0 += __half2float(h0) + __half2float(h1);
                s1 += __half2float(h2v) + __half2float(h3);
                __half2 o0; o0.x = h0;  o0.y = h1;
                __half2 o1; o1.x = h2v; o1.y = h3;
                *(__half2*)(C + (size_t)b*cBatch + (size_t)r0*cld + col) = o0;
                *(__half2*)(C + (size_t)b*cBatch + (size_t)r1*cld + col) = o1;
            }
            s0 += __shfl_xor_sync(0xffffffffu, s0, 1);
            s0 += __shfl_xor_sync(0xffffffffu, s0, 2);
            s1 += __shfl_xor_sync(0xffffffffu, s1, 1);
            s1 += __shfl_xor_sync(0xffffffffu, s1, 2);
            if (tig == 0) {
                atomicAdd(&g_rowsum[b*SEQ + r0], s0);
                atomicAdd(&g_rowsum[b*SEQ + r1], s1);
            }
        } else {
            float* C = (float*)Cbase;
            float inv0 = 1.0f / g_rowsum[b*SEQ + r0];
            float inv1 = 1.0f / g_rowsum[b*SEQ + r1];
            #pragma unroll
            for (int bn = 0; bn < 4; bn++) {
                const int col = nt*128 + warp_n*32 + bn*8 + 2*tig;
                float2 o0; o0.x = acc[am][bn][0]*inv0; o0.y = acc[am][bn][1]*inv0;
                float2 o1; o1.x = acc[am][bn][2]*inv1; o1.y = acc[am][bn][3]*inv1;
                *(float2*)(C + (size_t)b*cBatch + (size_t)r0*cld + col) = o0;
                *(float2*)(C + (size_t)b*cBatch + (size_t)r1*cld + col) = o1;
            }
        }
    }
}

// ---------------- launcher ----------------
extern "C" void kernel_launch(void* const* d_in, const int* in_sizes, int n_in,
                              void* d_out, int out_size)
{
    const float* x  = (const float*)d_in[0];
    const float* Wq = (const float*)d_in[1];
    const float* bq = (const float*)d_in[2];
    const float* Wk = (const float*)d_in[3];
    const float* bk = (const float*)d_in[4];
    const float* Wv = (const float*)d_in[5];
    const float* bv = (const float*)d_in[6];
    float* out = (float*)d_out;

    cudaFuncSetAttribute(qkv_proj_mma_kernel, cudaFuncAttributeMaxDynamicSharedMemorySize, SMEM_PROJ);
    cudaFuncSetAttribute(gemm_f16_kernel, cudaFuncAttributeMaxDynamicSharedMemorySize, SMEM_GEMM);

    __half *g_Q_p, *g_K_p, *g_Vt_p, *g_P_p;
    cudaGetSymbolAddress((void**)&g_Q_p,  g_Q);
    cudaGetSymbolAddress((void**)&g_K_p,  g_K);
    cudaGetSymbolAddress((void**)&g_Vt_p, g_Vt);
    cudaGetSymbolAddress((void**)&g_P_p,  g_P);

    // 1) convert x/W to fp16 (+ W transpose), zero rowsums
    convert_kernel<<<1088, 256>>>(x, Wq, Wk, Wv);

    // 2) tensor-core QKV projections
    qkv_proj_mma_kernel<<<dim3(4, 256, 3), 256, SMEM_PROJ>>>(bq, bk, bv);

    // 3) P = exp(Q.K^T), rowsum accumulated
    dim3 sg(SEQ/128, SEQ/128, BATCH);   // (32, 32, 8)
    gemm_f16_kernel<<<sg, 256, SMEM_GEMM>>>(
        g_Q_p, g_K_p, (void*)g_P_p,
        HID, (size_t)SEQ*HID, (size_t)SEQ*HID, (size_t)SEQ*SEQ, SEQ, 0);

    // 4) O = (P.Vt^T) / rowsum
    dim3 og(HID/128, SEQ/128, BATCH);   // (4, 32, 8)
    gemm_f16_kernel<<<og, 256, SMEM_GEMM>>>(
        g_P_p, g_Vt_p, (void*)out,
        SEQ, (size_t)SEQ*SEQ, (size_t)HID*SEQ, (size_t)SEQ*HID, HID, 1);
}

// round 13
// speedup vs baseline: 22.3290x; 1.0454x over previous
#include <cuda_runtime.h>
#include <cuda_fp16.h>
#include <cstdint>
#include <math.h>

#define BATCH 8
#define SEQ   4096
#define DIN   64
#define HID   512
#define M_ROWS (BATCH*SEQ)
#define RSCALE 0.044194173824159216f  /* 1/sqrt(512) */

// ---------------- global scratch (allocation-free rule) ----------------
__device__ __half g_Xh[(size_t)M_ROWS*DIN];      // x in fp16
__device__ __half g_Wt[3*(size_t)HID*DIN];       // W^T fp16: [w][h][d]
__device__ __half g_Q [(size_t)BATCH*SEQ*HID];   // scaled by RSCALE
__device__ __half g_K [(size_t)BATCH*SEQ*HID];
__device__ __half g_Vt[(size_t)BATCH*HID*SEQ];   // V^T [b][h][s]
__device__ __half g_P [(size_t)BATCH*SEQ*SEQ];   // probs fp16 (256 MB)
__device__ float  g_rowsum[BATCH*SEQ];

// ======================= helpers =======================
__device__ __forceinline__ uint32_t smem_u32(const void* p) {
    uint32_t a;
    asm("{ .reg .u64 t; cvta.to.shared.u64 t, %1; cvt.u32.u64 %0, t; }" : "=r"(a) : "l"(p));
    return a;
}
__device__ __forceinline__ void cp16(uint32_t saddr, const void* g) {
    asm volatile("cp.async.cg.shared.global [%0], [%1], 16;"
                 :: "r"(saddr), "l"(__cvta_generic_to_global(g)) : "memory");
}
__device__ __forceinline__ void mma_f16(float* d, const uint32_t* a, const uint32_t* b) {
    asm volatile(
        "mma.sync.aligned.m16n8k16.row.col.f32.f16.f16.f32 "
        "{%0,%1,%2,%3}, {%4,%5,%6,%7}, {%8,%9}, {%0,%1,%2,%3};"
        : "+f"(d[0]), "+f"(d[1]), "+f"(d[2]), "+f"(d[3])
        : "r"(a[0]), "r"(a[1]), "r"(a[2]), "r"(a[3]), "r"(b[0]), "r"(b[1]));
}
__device__ __forceinline__ void ldsm_x4(uint32_t& r0, uint32_t& r1, uint32_t& r2, uint32_t& r3,
                                        uint32_t addr) {
    asm volatile("ldmatrix.sync.aligned.m8n8.x4.shared.b16 {%0,%1,%2,%3}, [%4];"
                 : "=r"(r0), "=r"(r1), "=r"(r2), "=r"(r3) : "r"(addr));
}
__device__ __forceinline__ uint32_t pack2(float a, float b) {
    __half2 h = __floats2half2_rn(a, b);
    return *(uint32_t*)&h;
}

// ---------------- convert: xh, W^T fp16, zero rowsum ----------------
__global__ __launch_bounds__(256) void convert_kernel(
    const float* __restrict__ x,
    const float* __restrict__ Wq, const float* __restrict__ Wk, const float* __restrict__ Wv)
{
    const int bid = blockIdx.x, tid = threadIdx.x;
    if (bid < 1024) {
        size_t i8 = ((size_t)bid*256 + tid)*8;
        float4 a = *(const float4*)&x[i8];
        float4 b = *(const float4*)&x[i8+4];
        uint4 o;
        o.x = pack2(a.x, a.y); o.y = pack2(a.z, a.w);
        o.z = pack2(b.x, b.y); o.w = pack2(b.z, b.w);
        *(uint4*)&g_Xh[i8] = o;
    } else if (bid < 1072) {
        int t = (bid - 1024)*256 + tid;
        int w = t / 4096;
        int r = t - w*4096;
        int h = r >> 3;
        int d0 = (r & 7)*8;
        const float* W = (w == 0) ? Wq : (w == 1) ? Wk : Wv;
        float f[8];
        #pragma unroll
        for (int j = 0; j < 8; j++) f[j] = W[(size_t)(d0+j)*HID + h];
        uint4 o;
        o.x = pack2(f[0], f[1]); o.y = pack2(f[2], f[3]);
        o.z = pack2(f[4], f[5]); o.w = pack2(f[6], f[7]);
        *(uint4*)&g_Wt[(size_t)w*HID*DIN + (size_t)h*DIN + d0] = o;
    } else {
        int i = ((bid - 1072)*256 + tid)*8;
        #pragma unroll
        for (int j = 0; j < 8; j++) g_rowsum[i+j] = 0.0f;
    }
}

// ---------------- tensor-core QKV projection (unchanged structure) ----------------
#define PT 136
#define SMEM_PROJ (32768 + PT*128*2)

__global__ __launch_bounds__(256) void qkv_proj_mma_kernel(
    const float* __restrict__ bq, const float* __restrict__ bk, const float* __restrict__ bv)
{
    extern __shared__ char sm[];
    const uint32_t smem_base = smem_u32(sm);
    const int tid = threadIdx.x;
    const int wid = tid >> 5, lane = tid & 31;
    const int warp_m = wid >> 2, warp_n = wid & 3;
    const int g = lane >> 2, tig = lane & 3;
    const int z = blockIdx.z, mt = blockIdx.y, nt = blockIdx.x;

    const __half* A = g_Xh + (size_t)mt*128*DIN;
    const __half* B = g_Wt + (size_t)z*HID*DIN + (size_t)nt*128*DIN;
    const float* bias = (z == 0) ? bq : (z == 1) ? bk : bv;

    const int ldrow = tid >> 3, ldf4 = tid & 7;
    const uint32_t sRow = (uint32_t)ldrow*128 + (uint32_t)((ldf4 ^ (ldrow & 7))*16);
    const size_t gOff = (size_t)ldrow*DIN + ldf4*8;
    #pragma unroll
    for (int i = 0; i < 4; i++) {
        cp16(smem_base + sRow + i*4096,         A + gOff + (size_t)i*32*DIN);
        cp16(smem_base + 16384 + sRow + i*4096, B + gOff + (size_t)i*32*DIN);
    }
    asm volatile("cp.async.commit_group;" ::: "memory");
    asm volatile("cp.async.wait_group 0;" ::: "memory");
    __syncthreads();

    const int lrow8 = lane & 7;
    const int rowA = lrow8 + 8*((lane >> 3) & 1);
    const int kcA  = lane >> 4;
    const int rowB = lrow8 + 8*(lane >> 4);
    const int kcB  = (lane >> 3) & 1;
    const uint32_t aB = smem_base + (uint32_t)(warp_m*64 + rowA)*128;
    const uint32_t bB = smem_base + 16384 + (uint32_t)(warp_n*32 + rowB)*128;

    float acc[4][4][4];
    #pragma unroll
    for (int i = 0; i < 4; i++)
        #pragma unroll
        for (int j = 0; j < 4; j++)
            #pragma unroll
            for (int v = 0; v < 4; v++) acc[i][j][v] = 0.0f;

    #pragma unroll
    for (int kk = 0; kk < 4; kk++) {
        const uint32_t xA = (uint32_t)(((2*kk + kcA) ^ lrow8)*16);
        const uint32_t xB = (uint32_t)(((2*kk + kcB) ^ lrow8)*16);
        uint32_t af[4][4];
        #pragma unroll
        for (int am = 0; am < 4; am++)
            ldsm_x4(af[am][0], af[am][1], af[am][2], af[am][3], aB + am*2048 + xA);
        uint32_t bf[2][4];
        ldsm_x4(bf[0][0], bf[0][1], bf[0][2], bf[0][3], bB + xB);
        ldsm_x4(bf[1][0], bf[1][1], bf[1][2], bf[1][3], bB + 2048 + xB);
        #pragma unroll
        for (int am = 0; am < 4; am++)
            #pragma unroll
            for (int bn = 0; bn < 4; bn++)
                mma_f16(acc[am][bn], af[am], &bf[bn >> 1][2*(bn & 1)]);
    }

    float b0[4], b1[4];
    #pragma unroll
    for (int bn = 0; bn < 4; bn++) {
        int gcol = nt*128 + warp_n*32 + bn*8 + 2*tig;
        b0[bn] = __ldg(&bias[gcol]);
        b1[bn] = __ldg(&bias[gcol+1]);
    }

    if (z < 2) {
        __half* osel = (z == 0) ? g_Q : g_K;
        const float sc = (z == 0) ? RSCALE : 1.0f;
        #pragma unroll
        for (int am = 0; am < 4; am++) {
            const int r0 = mt*128 + warp_m*64 + am*16 + g;
            const int r1 = r0 + 8;
            #pragma unroll
            for (int bn = 0; bn < 4; bn++) {
                const int gcol = nt*128 + warp_n*32 + bn*8 + 2*tig;
                *(uint32_t*)(osel + (size_t)r0*HID + gcol) =
                    pack2((acc[am][bn][0]+b0[bn])*sc, (acc[am][bn][1]+b1[bn])*sc);
                *(uint32_t*)(osel + (size_t)r1*HID + gcol) =
                    pack2((acc[am][bn][2]+b0[bn])*sc, (acc[am][bn][3]+b1[bn])*sc);
            }
        }
    } else {
        __half* smT = (__half*)(sm + 32768);
        #pragma unroll
        for (int am = 0; am < 4; am++) {
            const int r0 = warp_m*64 + am*16 + g;
            const int r1 = r0 + 8;
            #pragma unroll
            for (int bn = 0; bn < 4; bn++) {
                const int col = warp_n*32 + bn*8 + 2*tig;
                smT[(col  )*PT + r0] = __float2half_rn(acc[am][bn][0]+b0[bn]);
                smT[(col+1)*PT + r0] = __float2half_rn(acc[am][bn][1]+b1[bn]);
                smT[(col  )*PT + r1] = __float2half_rn(acc[am][bn][2]+b0[bn]);
                smT[(col+1)*PT + r1] = __float2half_rn(acc[am][bn][3]+b1[bn]);
            }
        }
        __syncthreads();
        const int bb = mt >> 5;
        const int s0 = (mt*128) & (SEQ-1);
        #pragma unroll
        for (int j = 0; j < 8; j++) {
            int idx = j*256 + tid;
            int h  = idx >> 4;
            int ch = idx & 15;
            uint4 v = *(uint4*)&smT[h*PT + ch*8];
            *(uint4*)&g_Vt[((size_t)bb*HID + nt*128 + h)*SEQ + s0 + ch*8] = v;
        }
    }
}

// ======================= fp16 mma.sync GEMM (4 warps, 64x64 warp tile) =======================
// C[128,128] per CTA; 128 threads; 4 warps as 2(M) x 2(N); warp tile 64x64.
// K chunked by 64 halves. 3-stage cp.async pipeline, one sync per chunk.
// mode 0: P = fp16(exp(A.B^T)), atomicAdd row sums
// mode 1: O = (A.B^T)/rowsum, fp32
#define KCH 64
#define TILEB (128*128)               // 16384 B
#define STAGEB (2*TILEB)              // 32768 B (A + B)
#define NSTAGE 3
#define SMEM_GEMM (NSTAGE*STAGEB)     // 98304 B

__global__ __launch_bounds__(128, 2) void gemm_f16_kernel(
    const __half* __restrict__ Abase, const __half* __restrict__ Bbase,
    void* __restrict__ Cbase,
    int Kdim, size_t aBatch, size_t bBatch, size_t cBatch, int cld, int mode)
{
    extern __shared__ char sm[];
    const int tid  = threadIdx.x;
    const int wid  = tid >> 5, lane = tid & 31;
    const int warp_m = wid >> 1, warp_n = wid & 1;
    const int g = lane >> 2, tig = lane & 3;
    const int b = blockIdx.z, mt = blockIdx.y, nt = blockIdx.x;

    const __half* A = Abase + (size_t)b*aBatch + (size_t)mt*128*Kdim;
    const __half* B = Bbase + (size_t)b*bBatch + (size_t)nt*128*Kdim;

    const uint32_t smem_base = smem_u32(sm);

    // cp.async: 128 threads, 16 rows/pass x 8 chunks, 8 passes per tile
    const int ldrow = tid >> 3, ldf4 = tid & 7;
    const uint32_t sRow = (uint32_t)ldrow*128 + (uint32_t)((ldf4 ^ (ldrow & 7)) * 16);
    const size_t aRowOff = (size_t)ldrow*Kdim + ldf4*8;
    const size_t rowStep = (size_t)16*Kdim;

    const int lrow8 = lane & 7;
    const int rowA = lrow8 + 8*((lane >> 3) & 1);
    const int kcA  = lane >> 4;
    const int rowB = lrow8 + 8*(lane >> 4);
    const int kcB  = (lane >> 3) & 1;
    const uint32_t aBase0 = smem_base + (uint32_t)(warp_m*64 + rowA)*128;
    const uint32_t bBase0 = smem_base + TILEB + (uint32_t)(warp_n*64 + rowB)*128;
    uint32_t xA[4], xB[4];
    #pragma unroll
    for (int kk = 0; kk < 4; kk++) {
        xA[kk] = (uint32_t)(((2*kk + kcA) ^ lrow8) * 16);
        xB[kk] = (uint32_t)(((2*kk + kcB) ^ lrow8) * 16);
    }

    float acc[4][8][4];
    #pragma unroll
    for (int i = 0; i < 4; i++)
        #pragma unroll
        for (int j = 0; j < 8; j++)
            #pragma unroll
            for (int v = 0; v < 4; v++) acc[i][j][v] = 0.0f;

    const int NCH = Kdim / KCH;

    // ---- prologue: chunks 0,1 -> stages 0,1 ----
    #pragma unroll
    for (int p = 0; p < 2; p++) {
        const __half* Ak = A + p*KCH;
        const __half* Bk = B + p*KCH;
        uint32_t st = smem_base + (uint32_t)p*STAGEB;
        #pragma unroll
        for (int i = 0; i < 8; i++) {
            cp16(st + sRow + i*2048,         Ak + aRowOff + i*rowStep);
            cp16(st + TILEB + sRow + i*2048, Bk + aRowOff + i*rowStep);
        }
        asm volatile("cp.async.commit_group;" ::: "memory");
    }

    const __half* gA = A + 2*KCH;
    const __half* gB = B + 2*KCH;
    int stR = 0, stW = 2;

    for (int c = 0; c < NCH; ++c) {
        asm volatile("cp.async.wait_group 1;" ::: "memory");   // chunk c resident
        __syncthreads();                                       // reads of stage stW done

        if (c + 2 < NCH) {
            uint32_t st = smem_base + (uint32_t)stW*STAGEB;
            #pragma unroll
            for (int i = 0; i < 8; i++) {
                cp16(st + sRow + i*2048,         gA + aRowOff + i*rowStep);
                cp16(st + TILEB + sRow + i*2048, gB + aRowOff + i*rowStep);
            }
            gA += KCH; gB += KCH;
        }
        asm volatile("cp.async.commit_group;" ::: "memory");

        const uint32_t aB = aBase0 + (uint32_t)stR*STAGEB;
        const uint32_t bB = bBase0 + (uint32_t)stR*STAGEB;

        #pragma unroll
        for (int kk = 0; kk < 4; kk++) {
            uint32_t af[4][4];
            #pragma unroll
            for (int am = 0; am < 4; am++)
                ldsm_x4(af[am][0], af[am][1], af[am][2], af[am][3],
                        aB + am*2048 + xA[kk]);
            uint32_t bf[4][4];
            #pragma unroll
            for (int bq = 0; bq < 4; bq++)
                ldsm_x4(bf[bq][0], bf[bq][1], bf[bq][2], bf[bq][3],
                        bB + bq*2048 + xB[kk]);
            #pragma unroll
            for (int am = 0; am < 4; am++)
                #pragma unroll
                for (int bn = 0; bn < 8; bn++)
                    mma_f16(acc[am][bn], af[am], &bf[bn >> 1][2*(bn & 1)]);
        }
        stR = (stR == 2) ? 0 : stR + 1;
        stW = (stW == 2) ? 0 : stW + 1;
    }

    // ================= epilogue =================
    #pragma unroll
    for (int am = 0; am < 4; am++) {
        const int r0 = mt*128 + warp_m*64 + am*16 + g;
        const int r1 = r0 + 8;
        if (mode == 0) {
            __half* C = (__half*)Cbase;
            float s0 = 0.0f, s1 = 0.0f;
            #pragma unroll
            for (int bn = 0; bn < 8; bn++) {
                const int col = nt*128 + warp_n*64 + bn*8 + 2*tig;
                __half h0 = __float2half_rn(__expf(acc[am][bn][0]));
                __half h1 = __float2half_rn(__expf(acc[am][bn][1]));
                __half h2v = __float2half_rn(__expf(acc[am][bn][2]));
                __half h3 = __float2half_rn(__expf(acc[am][bn][3]));
                s0 += __half2float(h0) + __half2float(h1);
                s1 += __half2float(h2v) + __half2float(h3);
                __half2 o0; o0.x = h0;  o0.y = h1;
                __half2 o1; o1.x = h2v; o1.y = h3;
                *(__half2*)(C + (size_t)b*cBatch + (size_t)r0*cld + col) = o0;
                *(__half2*)(C + (size_t)b*cBatch + (size_t)r1*cld + col) = o1;
            }
            s0 += __shfl_xor_sync(0xffffffffu, s0, 1);
            s0 += __shfl_xor_sync(0xffffffffu, s0, 2);
            s1 += __shfl_xor_sync(0xffffffffu, s1, 1);
            s1 += __shfl_xor_sync(0xffffffffu, s1, 2);
            if (tig == 0) {
                atomicAdd(&g_rowsum[b*SEQ + r0], s0);
                atomicAdd(&g_rowsum[b*SEQ + r1], s1);
            }
        } else {
            float* C = (float*)Cbase;
            float inv0 = 1.0f / g_rowsum[b*SEQ + r0];
            float inv1 = 1.0f / g_rowsum[b*SEQ + r1];
            #pragma unroll
            for (int bn = 0; bn < 8; bn++) {
                const int col = nt*128 + warp_n*64 + bn*8 + 2*tig;
                float2 o0; o0.x = acc[am][bn][0]*inv0; o0.y = acc[am][bn][1]*inv0;
                float2 o1; o1.x = acc[am][bn][2]*inv1; o1.y = acc[am][bn][3]*inv1;
                *(float2*)(C + (size_t)b*cBatch + (size_t)r0*cld + col) = o0;
                *(float2*)(C + (size_t)b*cBatch + (size_t)r1*cld + col) = o1;
            }
        }
    }
}

// ---------------- launcher ----------------
extern "C" void kernel_launch(void* const* d_in, const int* in_sizes, int n_in,
                              void* d_out, int out_size)
{
    const float* x  = (const float*)d_in[0];
    const float* Wq = (const float*)d_in[1];
    const float* bq = (const float*)d_in[2];
    const float* Wk = (const float*)d_in[3];
    const float* bk = (const float*)d_in[4];
    const float* Wv = (const float*)d_in[5];
    const float* bv = (const float*)d_in[6];
    float* out = (float*)d_out;

    cudaFuncSetAttribute(qkv_proj_mma_kernel, cudaFuncAttributeMaxDynamicSharedMemorySize, SMEM_PROJ);
    cudaFuncSetAttribute(gemm_f16_kernel, cudaFuncAttributeMaxDynamicSharedMemorySize, SMEM_GEMM);

    __half *g_Q_p, *g_K_p, *g_Vt_p, *g_P_p;
    cudaGetSymbolAddress((void**)&g_Q_p,  g_Q);
    cudaGetSymbolAddress((void**)&g_K_p,  g_K);
    cudaGetSymbolAddress((void**)&g_Vt_p, g_Vt);
    cudaGetSymbolAddress((void**)&g_P_p,  g_P);

    // 1) convert x/W to fp16 (+ W transpose), zero rowsums
    convert_kernel<<<1088, 256>>>(x, Wq, Wk, Wv);

    // 2) tensor-core QKV projections
    qkv_proj_mma_kernel<<<dim3(4, 256, 3), 256, SMEM_PROJ>>>(bq, bk, bv);

    // 3) P = exp(Q.K^T), rowsum accumulated
    dim3 sg(SEQ/128, SEQ/128, BATCH);   // (32, 32, 8)
    gemm_f16_kernel<<<sg, 128, SMEM_GEMM>>>(
        g_Q_p, g_K_p, (void*)g_P_p,
        HID, (size_t)SEQ*HID, (size_t)SEQ*HID, (size_t)SEQ*SEQ, SEQ, 0);

    // 4) O = (P.Vt^T) / rowsum
    dim3 og(HID/128, SEQ/128, BATCH);   // (4, 32, 8)
    gemm_f16_kernel<<<og, 128, SMEM_GEMM>>>(
        g_P_p, g_Vt_p, (void*)out,
        SEQ, (size_t)SEQ*SEQ, (size_t)HID*SEQ, (size_t)SEQ*HID, HID, 1);
}

// round 14
// speedup vs baseline: 23.3958x; 1.0478x over previous
#include <cuda_runtime.h>
#include <cuda_fp16.h>
#include <cstdint>
#include <math.h>

#define BATCH 8
#define SEQ   4096
#define DIN   64
#define HID   512
#define M_ROWS (BATCH*SEQ)
#define RSCALE 0.044194173824159216f  /* 1/sqrt(512) */

// ---------------- global scratch (allocation-free rule) ----------------
__device__ __half g_Xh[(size_t)M_ROWS*DIN];      // x in fp16
__device__ __half g_Wt[3*(size_t)HID*DIN];       // W^T fp16: [w][h][d]
__device__ __half g_Q [(size_t)BATCH*SEQ*HID];   // scaled by RSCALE
__device__ __half g_K [(size_t)BATCH*SEQ*HID];
__device__ __half g_Vt[(size_t)BATCH*HID*SEQ];   // V^T [b][h][s]
__device__ __half g_P [(size_t)BATCH*SEQ*SEQ];   // probs fp16 (256 MB)
__device__ float  g_rowsum[BATCH*SEQ];

// ======================= helpers =======================
__device__ __forceinline__ uint32_t smem_u32(const void* p) {
    uint32_t a;
    asm("{ .reg .u64 t; cvta.to.shared.u64 t, %1; cvt.u32.u64 %0, t; }" : "=r"(a) : "l"(p));
    return a;
}
__device__ __forceinline__ void cp16(uint32_t saddr, const void* g) {
    asm volatile("cp.async.cg.shared.global [%0], [%1], 16;"
                 :: "r"(saddr), "l"(__cvta_generic_to_global(g)) : "memory");
}
__device__ __forceinline__ void mma_f16(float* d, const uint32_t* a, const uint32_t* b) {
    asm volatile(
        "mma.sync.aligned.m16n8k16.row.col.f32.f16.f16.f32 "
        "{%0,%1,%2,%3}, {%4,%5,%6,%7}, {%8,%9}, {%0,%1,%2,%3};"
        : "+f"(d[0]), "+f"(d[1]), "+f"(d[2]), "+f"(d[3])
        : "r"(a[0]), "r"(a[1]), "r"(a[2]), "r"(a[3]), "r"(b[0]), "r"(b[1]));
}
__device__ __forceinline__ void ldsm_x4(uint32_t& r0, uint32_t& r1, uint32_t& r2, uint32_t& r3,
                                        uint32_t addr) {
    asm volatile("ldmatrix.sync.aligned.m8n8.x4.shared.b16 {%0,%1,%2,%3}, [%4];"
                 : "=r"(r0), "=r"(r1), "=r"(r2), "=r"(r3) : "r"(addr));
}
__device__ __forceinline__ uint32_t pack2(float a, float b) {
    __half2 h = __floats2half2_rn(a, b);
    return *(uint32_t*)&h;
}

// ---------------- convert: xh, W^T fp16, zero rowsum ----------------
__global__ __launch_bounds__(256) void convert_kernel(
    const float* __restrict__ x,
    const float* __restrict__ Wq, const float* __restrict__ Wk, const float* __restrict__ Wv)
{
    const int bid = blockIdx.x, tid = threadIdx.x;
    if (bid < 1024) {
        size_t i8 = ((size_t)bid*256 + tid)*8;
        float4 a = *(const float4*)&x[i8];
        float4 b = *(const float4*)&x[i8+4];
        uint4 o;
        o.x = pack2(a.x, a.y); o.y = pack2(a.z, a.w);
        o.z = pack2(b.x, b.y); o.w = pack2(b.z, b.w);
        *(uint4*)&g_Xh[i8] = o;
    } else if (bid < 1072) {
        int t = (bid - 1024)*256 + tid;
        int w = t / 4096;
        int r = t - w*4096;
        int h = r >> 3;
        int d0 = (r & 7)*8;
        const float* W = (w == 0) ? Wq : (w == 1) ? Wk : Wv;
        float f[8];
        #pragma unroll
        for (int j = 0; j < 8; j++) f[j] = W[(size_t)(d0+j)*HID + h];
        uint4 o;
        o.x = pack2(f[0], f[1]); o.y = pack2(f[2], f[3]);
        o.z = pack2(f[4], f[5]); o.w = pack2(f[6], f[7]);
        *(uint4*)&g_Wt[(size_t)w*HID*DIN + (size_t)h*DIN + d0] = o;
    } else {
        int i = ((bid - 1072)*256 + tid)*8;
        #pragma unroll
        for (int j = 0; j < 8; j++) g_rowsum[i+j] = 0.0f;
    }
}

// ---------------- tensor-core QKV projection ----------------
#define PT 136
#define SMEM_PROJ (32768 + PT*128*2)

__global__ __launch_bounds__(256) void qkv_proj_mma_kernel(
    const float* __restrict__ bq, const float* __restrict__ bk, const float* __restrict__ bv)
{
    extern __shared__ char sm[];
    const uint32_t smem_base = smem_u32(sm);
    const int tid = threadIdx.x;
    const int wid = tid >> 5, lane = tid & 31;
    const int warp_m = wid >> 2, warp_n = wid & 3;
    const int g = lane >> 2, tig = lane & 3;
    const int z = blockIdx.z, mt = blockIdx.y, nt = blockIdx.x;

    const __half* A = g_Xh + (size_t)mt*128*DIN;
    const __half* B = g_Wt + (size_t)z*HID*DIN + (size_t)nt*128*DIN;
    const float* bias = (z == 0) ? bq : (z == 1) ? bk : bv;

    const int ldrow = tid >> 3, ldf4 = tid & 7;
    const uint32_t sRow = (uint32_t)ldrow*128 + (uint32_t)((ldf4 ^ (ldrow & 7))*16);
    const size_t gOff = (size_t)ldrow*DIN + ldf4*8;
    #pragma unroll
    for (int i = 0; i < 4; i++) {
        cp16(smem_base + sRow + i*4096,         A + gOff + (size_t)i*32*DIN);
        cp16(smem_base + 16384 + sRow + i*4096, B + gOff + (size_t)i*32*DIN);
    }
    asm volatile("cp.async.commit_group;" ::: "memory");
    asm volatile("cp.async.wait_group 0;" ::: "memory");
    __syncthreads();

    const int lrow8 = lane & 7;
    const int rowA = lrow8 + 8*((lane >> 3) & 1);
    const int kcA  = lane >> 4;
    const int rowB = lrow8 + 8*(lane >> 4);
    const int kcB  = (lane >> 3) & 1;
    const uint32_t aB = smem_base + (uint32_t)(warp_m*64 + rowA)*128;
    const uint32_t bB = smem_base + 16384 + (uint32_t)(warp_n*32 + rowB)*128;

    float acc[4][4][4];
    #pragma unroll
    for (int i = 0; i < 4; i++)
        #pragma unroll
        for (int j = 0; j < 4; j++)
            #pragma unroll
            for (int v = 0; v < 4; v++) acc[i][j][v] = 0.0f;

    #pragma unroll
    for (int kk = 0; kk < 4; kk++) {
        const uint32_t xA = (uint32_t)(((2*kk + kcA) ^ lrow8)*16);
        const uint32_t xB = (uint32_t)(((2*kk + kcB) ^ lrow8)*16);
        uint32_t af[4][4];
        #pragma unroll
        for (int am = 0; am < 4; am++)
            ldsm_x4(af[am][0], af[am][1], af[am][2], af[am][3], aB + am*2048 + xA);
        uint32_t bf[2][4];
        ldsm_x4(bf[0][0], bf[0][1], bf[0][2], bf[0][3], bB + xB);
        ldsm_x4(bf[1][0], bf[1][1], bf[1][2], bf[1][3], bB + 2048 + xB);
        #pragma unroll
        for (int am = 0; am < 4; am++)
            #pragma unroll
            for (int bn = 0; bn < 4; bn++)
                mma_f16(acc[am][bn], af[am], &bf[bn >> 1][2*(bn & 1)]);
    }

    float b0[4], b1[4];
    #pragma unroll
    for (int bn = 0; bn < 4; bn++) {
        int gcol = nt*128 + warp_n*32 + bn*8 + 2*tig;
        b0[bn] = __ldg(&bias[gcol]);
        b1[bn] = __ldg(&bias[gcol+1]);
    }

    if (z < 2) {
        __half* osel = (z == 0) ? g_Q : g_K;
        const float sc = (z == 0) ? RSCALE : 1.0f;
        #pragma unroll
        for (int am = 0; am < 4; am++) {
            const int r0 = mt*128 + warp_m*64 + am*16 + g;
            const int r1 = r0 + 8;
            #pragma unroll
            for (int bn = 0; bn < 4; bn++) {
                const int gcol = nt*128 + warp_n*32 + bn*8 + 2*tig;
                *(uint32_t*)(osel + (size_t)r0*HID + gcol) =
                    pack2((acc[am][bn][0]+b0[bn])*sc, (acc[am][bn][1]+b1[bn])*sc);
                *(uint32_t*)(osel + (size_t)r1*HID + gcol) =
                    pack2((acc[am][bn][2]+b0[bn])*sc, (acc[am][bn][3]+b1[bn])*sc);
            }
        }
    } else {
        __half* smT = (__half*)(sm + 32768);
        #pragma unroll
        for (int am = 0; am < 4; am++) {
            const int r0 = warp_m*64 + am*16 + g;
            const int r1 = r0 + 8;
            #pragma unroll
            for (int bn = 0; bn < 4; bn++) {
                const int col = warp_n*32 + bn*8 + 2*tig;
                smT[(col  )*PT + r0] = __float2half_rn(acc[am][bn][0]+b0[bn]);
                smT[(col+1)*PT + r0] = __float2half_rn(acc[am][bn][1]+b1[bn]);
                smT[(col  )*PT + r1] = __float2half_rn(acc[am][bn][2]+b0[bn]);
                smT[(col+1)*PT + r1] = __float2half_rn(acc[am][bn][3]+b1[bn]);
            }
        }
        __syncthreads();
        const int bb = mt >> 5;
        const int s0 = (mt*128) & (SEQ-1);
        #pragma unroll
        for (int j = 0; j < 8; j++) {
            int idx = j*256 + tid;
            int h  = idx >> 4;
            int ch = idx & 15;
            uint4 v = *(uint4*)&smT[h*PT + ch*8];
            *(uint4*)&g_Vt[((size_t)bb*HID + nt*128 + h)*SEQ + s0 + ch*8] = v;
        }
    }
}

// ======================= fp16 mma.sync GEMM (spread prefetch) =======================
// C[128,128] per CTA; 128 threads; 4 warps as 2(M) x 2(N); warp tile 64x64.
// K chunked by 64 halves. 3-stage cp.async pipeline, one sync per chunk,
// prefetch cp.asyncs interleaved into the MMA stream (4 per kk-group).
// mode 0: P = fp16(exp(A.B^T)), atomicAdd row sums
// mode 1: O = (A.B^T)/rowsum, fp32
#define KCH 64
#define TILEB (128*128)               // 16384 B
#define STAGEB (2*TILEB)              // 32768 B (A + B)
#define NSTAGE 3
#define SMEM_GEMM (NSTAGE*STAGEB)     // 98304 B

__global__ __launch_bounds__(128, 2) void gemm_f16_kernel(
    const __half* __restrict__ Abase, const __half* __restrict__ Bbase,
    void* __restrict__ Cbase,
    int Kdim, size_t aBatch, size_t bBatch, size_t cBatch, int cld, int mode)
{
    extern __shared__ char sm[];
    const int tid  = threadIdx.x;
    const int wid  = tid >> 5, lane = tid & 31;
    const int warp_m = wid >> 1, warp_n = wid & 1;
    const int g = lane >> 2, tig = lane & 3;
    const int b = blockIdx.z, mt = blockIdx.y, nt = blockIdx.x;

    const __half* A = Abase + (size_t)b*aBatch + (size_t)mt*128*Kdim;
    const __half* B = Bbase + (size_t)b*bBatch + (size_t)nt*128*Kdim;

    const uint32_t smem_base = smem_u32(sm);

    const int ldrow = tid >> 3, ldf4 = tid & 7;
    const uint32_t sRow = (uint32_t)ldrow*128 + (uint32_t)((ldf4 ^ (ldrow & 7)) * 16);
    const size_t aRowOff = (size_t)ldrow*Kdim + ldf4*8;
    const size_t rowStep = (size_t)16*Kdim;

    const int lrow8 = lane & 7;
    const int rowA = lrow8 + 8*((lane >> 3) & 1);
    const int kcA  = lane >> 4;
    const int rowB = lrow8 + 8*(lane >> 4);
    const int kcB  = (lane >> 3) & 1;
    const uint32_t aBase0 = smem_base + (uint32_t)(warp_m*64 + rowA)*128;
    const uint32_t bBase0 = smem_base + TILEB + (uint32_t)(warp_n*64 + rowB)*128;
    uint32_t xA[4], xB[4];
    #pragma unroll
    for (int kk = 0; kk < 4; kk++) {
        xA[kk] = (uint32_t)(((2*kk + kcA) ^ lrow8) * 16);
        xB[kk] = (uint32_t)(((2*kk + kcB) ^ lrow8) * 16);
    }

    float acc[4][8][4];
    #pragma unroll
    for (int i = 0; i < 4; i++)
        #pragma unroll
        for (int j = 0; j < 8; j++)
            #pragma unroll
            for (int v = 0; v < 4; v++) acc[i][j][v] = 0.0f;

    const int NCH = Kdim / KCH;

    // ---- prologue: chunks 0,1 -> stages 0,1 ----
    #pragma unroll
    for (int p = 0; p < 2; p++) {
        const __half* Ak = A + p*KCH;
        const __half* Bk = B + p*KCH;
        uint32_t st = smem_base + (uint32_t)p*STAGEB;
        #pragma unroll
        for (int i = 0; i < 8; i++) {
            cp16(st + sRow + i*2048,         Ak + aRowOff + i*rowStep);
            cp16(st + TILEB + sRow + i*2048, Bk + aRowOff + i*rowStep);
        }
        asm volatile("cp.async.commit_group;" ::: "memory");
    }

    const __half* gA = A + 2*KCH;
    const __half* gB = B + 2*KCH;
    int stR = 0, stW = 2;

    for (int c = 0; c < NCH; ++c) {
        asm volatile("cp.async.wait_group 1;" ::: "memory");   // chunk c resident
        __syncthreads();                                       // reads of stage stW done

        const bool pf = (c + 2 < NCH);
        const uint32_t stA = smem_base + (uint32_t)stW*STAGEB;
        const uint32_t aB = aBase0 + (uint32_t)stR*STAGEB;
        const uint32_t bB = bBase0 + (uint32_t)stR*STAGEB;

        #pragma unroll
        for (int kk = 0; kk < 4; kk++) {
            // fragment loads for this kk
            uint32_t af[4][4];
            #pragma unroll
            for (int am = 0; am < 4; am++)
                ldsm_x4(af[am][0], af[am][1], af[am][2], af[am][3],
                        aB + am*2048 + xA[kk]);
            uint32_t bf[4][4];
            #pragma unroll
            for (int bq = 0; bq < 4; bq++)
                ldsm_x4(bf[bq][0], bf[bq][1], bf[bq][2], bf[bq][3],
                        bB + bq*2048 + xB[kk]);
            // spread prefetch: 2 A rows + 2 B rows per kk (16 total per chunk)
            if (pf) {
                const int i0 = 2*kk, i1 = 2*kk + 1;
                cp16(stA + sRow + i0*2048,         gA + aRowOff + i0*rowStep);
                cp16(stA + sRow + i1*2048,         gA + aRowOff + i1*rowStep);
                cp16(stA + TILEB + sRow + i0*2048, gB + aRowOff + i0*rowStep);
                cp16(stA + TILEB + sRow + i1*2048, gB + aRowOff + i1*rowStep);
            }
            // MMAs
            #pragma unroll
            for (int am = 0; am < 4; am++)
                #pragma unroll
                for (int bn = 0; bn < 8; bn++)
                    mma_f16(acc[am][bn], af[am], &bf[bn >> 1][2*(bn & 1)]);
        }
        if (pf) { gA += KCH; gB += KCH; }
        asm volatile("cp.async.commit_group;" ::: "memory");   // one group per iter

        stR = (stR == 2) ? 0 : stR + 1;
        stW = (stW == 2) ? 0 : stW + 1;
    }

    // ================= epilogue =================
    #pragma unroll
    for (int am = 0; am < 4; am++) {
        const int r0 = mt*128 + warp_m*64 + am*16 + g;
        const int r1 = r0 + 8;
        if (mode == 0) {
            __half* C = (__half*)Cbase;
            float s0 = 0.0f, s1 = 0.0f;
            #pragma unroll
            for (int bn = 0; bn < 8; bn++) {
                const int col = nt*128 + warp_n*64 + bn*8 + 2*tig;
                __half h0 = __float2half_rn(__expf(acc[am][bn][0]));
                __half h1 = __float2half_rn(__expf(acc[am][bn][1]));
                __half h2v = __float2half_rn(__expf(acc[am][bn][2]));
                __half h3 = __float2half_rn(__expf(acc[am][bn][3]));
                s0 += __half2float(h0) + __half2float(h1);
                s1 += __half2float(h2v) + __half2float(h3);
                __half2 o0; o0.x = h0;  o0.y = h1;
                __half2 o1; o1.x = h2v; o1.y = h3;
                *(__half2*)(C + (size_t)b*cBatch + (size_t)r0*cld + col) = o0;
                *(__half2*)(C + (size_t)b*cBatch + (size_t)r1*cld + col) = o1;
            }
            s0 += __shfl_xor_sync(0xffffffffu, s0, 1);
            s0 += __shfl_xor_sync(0xffffffffu, s0, 2);
            s1 += __shfl_xor_sync(0xffffffffu, s1, 1);
            s1 += __shfl_xor_sync(0xffffffffu, s1, 2);
            if (tig == 0) {
                atomicAdd(&g_rowsum[b*SEQ + r0], s0);
                atomicAdd(&g_rowsum[b*SEQ + r1], s1);
            }
        } else {
            float* C = (float*)Cbase;
            float inv0 = 1.0f / g_rowsum[b*SEQ + r0];
            float inv1 = 1.0f / g_rowsum[b*SEQ + r1];
            #pragma unroll
            for (int bn = 0; bn < 8; bn++) {
                const int col = nt*128 + warp_n*64 + bn*8 + 2*tig;
                float2 o0; o0.x = acc[am][bn][0]*inv0; o0.y = acc[am][bn][1]*inv0;
                float2 o1; o1.x = acc[am][bn][2]*inv1; o1.y = acc[am][bn][3]*inv1;
                *(float2*)(C + (size_t)b*cBatch + (size_t)r0*cld + col) = o0;
                *(float2*)(C + (size_t)b*cBatch + (size_t)r1*cld + col) = o1;
            }
        }
    }
}

// ---------------- launcher ----------------
extern "C" void kernel_launch(void* const* d_in, const int* in_sizes, int n_in,
                              void* d_out, int out_size)
{
    const float* x  = (const float*)d_in[0];
    const float* Wq = (const float*)d_in[1];
    const float* bq = (const float*)d_in[2];
    const float* Wk = (const float*)d_in[3];
    const float* bk = (const float*)d_in[4];
    const float* Wv = (const float*)d_in[5];
    const float* bv = (const float*)d_in[6];
    float* out = (float*)d_out;

    cudaFuncSetAttribute(qkv_proj_mma_kernel, cudaFuncAttributeMaxDynamicSharedMemorySize, SMEM_PROJ);
    cudaFuncSetAttribute(gemm_f16_kernel, cudaFuncAttributeMaxDynamicSharedMemorySize, SMEM_GEMM);

    __half *g_Q_p, *g_K_p, *g_Vt_p, *g_P_p;
    cudaGetSymbolAddress((void**)&g_Q_p,  g_Q);
    cudaGetSymbolAddress((void**)&g_K_p,  g_K);
    cudaGetSymbolAddress((void**)&g_Vt_p, g_Vt);
    cudaGetSymbolAddress((void**)&g_P_p,  g_P);

    // 1) convert x/W to fp16 (+ W transpose), zero rowsums
    convert_kernel<<<1088, 256>>>(x, Wq, Wk, Wv);

    // 2) tensor-core QKV projections
    qkv_proj_mma_kernel<<<dim3(4, 256, 3), 256, SMEM_PROJ>>>(bq, bk, bv);

    // 3) P = exp(Q.K^T), rowsum accumulated
    dim3 sg(SEQ/128, SEQ/128, BATCH);   // (32, 32, 8)
    gemm_f16_kernel<<<sg, 128, SMEM_GEMM>>>(
        g_Q_p, g_K_p, (void*)g_P_p,
        HID, (size_t)SEQ*HID, (size_t)SEQ*HID, (size_t)SEQ*SEQ, SEQ, 0);

    // 4) O = (P.Vt^T) / rowsum
    dim3 og(HID/128, SEQ/128, BATCH);   // (4, 32, 8)
    gemm_f16_kernel<<<og, 128, SMEM_GEMM>>>(
        g_P_p, g_Vt_p, (void*)out,
        SEQ, (size_t)SEQ*SEQ, (size_t)HID*SEQ, (size_t)SEQ*HID, HID, 1);
}